// round 1
// baseline (speedup 1.0000x reference)
#include <cuda_runtime.h>
#include <math.h>

// ---------------- problem dims ----------------
constexpr int Bb = 16, Nn = 2000, Ee = 3000, Cc = 17, Ww = 12, Dd = 16, Oo = 256, Kk = 3, NBt = 3;
constexpr int BC    = Bb * Cc;       // 272 packed columns
constexpr int KC    = Kk * Cc;       // 51
constexpr int O4    = Oo / 4;        // 64
constexpr int WCOLS = KC * O4;       // 3264
constexpr int HCH   = 16;            // hodge K-split chunks
constexpr int MKS   = 4;             // inc GEMM K-splits

// ---------------- scratch (device globals, no allocation) ----------------
__device__ float g_S[Nn * Nn];
__device__ float g_rowsum[Nn];
__device__ float g_X [Nn * BC];
__device__ float g_R1[Nn * BC];
__device__ float g_R2[Nn * BC];
__device__ float g_W   [Nn * WCOLS];
__device__ float g_bias[Nn * Oo];
__device__ float g_wwt [Nn * 128];
__device__ float g_wws [Nn * 32];
__device__ float g_U[Bb * Ee];
__device__ float g_V[Bb * Ee];
__device__ float g_Hpart[HCH * Bb * Ee];
__device__ float g_Ybar[Bb * Ee];
__device__ float g_Mpart[MKS * Bb * Nn];
__device__ float g_XW[Bb * Nn];
__device__ float g_rs[Nn];

// Robust scalar decode: handles int32 / low-word-of-int64 / float32 storage.
__device__ __forceinline__ float scalar_val(const void* p) {
    int v = *(const int*)p;
    if (v > -100000000 && v < 100000000) return (float)v;
    return __int_as_float(v);
}

// ---------------- S0 = relu(ne @ ne^T), diag = stay ----------------
__global__ void k_s0(const float* __restrict__ ne, const void* p_stay) {
    __shared__ float a_s[16][17], b_s[16][17];
    int i0 = blockIdx.y * 16, j0 = blockIdx.x * 16;
    int t = threadIdx.x;
    int r = t >> 4, d = t & 15;
    a_s[r][d] = (i0 + r < Nn) ? ne[(i0 + r) * Dd + d] : 0.f;
    b_s[r][d] = (j0 + r < Nn) ? ne[(j0 + r) * Dd + d] : 0.f;
    __syncthreads();
    int ty = t >> 4, tx = t & 15;
    int i = i0 + ty, j = j0 + tx;
    if (i < Nn && j < Nn) {
        float acc = 0.f;
        #pragma unroll
        for (int dd = 0; dd < 16; dd++) acc += a_s[ty][dd] * b_s[tx][dd];
        acc = fmaxf(acc, 0.f);
        if (i == j) acc = scalar_val(p_stay);
        g_S[(size_t)i * Nn + j] = acc;
    }
}

// ---------------- row softmax (or adj*exp path) + row sums ----------------
__global__ void k_softmax(const void* p_fixed, const float* __restrict__ adj) {
    __shared__ float row[Nn];
    __shared__ float red[256];
    int i = blockIdx.x, t = threadIdx.x;
    bool fixed = (scalar_val(p_fixed) != 0.f);
    for (int j = t; j < Nn; j += 256) row[j] = g_S[(size_t)i * Nn + j];
    __syncthreads();
    float outsum;
    if (!fixed) {
        float m = -1e30f;
        for (int j = t; j < Nn; j += 256) m = fmaxf(m, row[j]);
        red[t] = m; __syncthreads();
        for (int s = 128; s > 0; s >>= 1) { if (t < s) red[t] = fmaxf(red[t], red[t + s]); __syncthreads(); }
        m = red[0]; __syncthreads();
        float s = 0.f;
        for (int j = t; j < Nn; j += 256) s += expf(row[j] - m);
        red[t] = s; __syncthreads();
        for (int st = 128; st > 0; st >>= 1) { if (t < st) red[t] += red[t + st]; __syncthreads(); }
        float inv = 1.f / red[0]; __syncthreads();
        float fs = 0.f;
        for (int j = t; j < Nn; j += 256) {
            float v = expf(row[j] - m) * inv;
            g_S[(size_t)i * Nn + j] = v;
            fs += v;
        }
        red[t] = fs; __syncthreads();
        for (int st = 128; st > 0; st >>= 1) { if (t < st) red[t] += red[t + st]; __syncthreads(); }
        outsum = red[0];
    } else {
        float fs = 0.f;
        for (int j = t; j < Nn; j += 256) {
            float v = adj[(size_t)i * Nn + j] * expf(row[j]);
            g_S[(size_t)i * Nn + j] = v;
            fs += v;
        }
        red[t] = fs; __syncthreads();
        for (int st = 128; st > 0; st >>= 1) { if (t < st) red[t] += red[t + st]; __syncthreads(); }
        outsum = red[0];
    }
    if (t == 0) g_rowsum[i] = outsum;
}

// ---------------- S[i,j] /= rowsum[j] (faithful column scale) ----------------
__global__ void k_colscale() {
    int idx = blockIdx.x * 256 + threadIdx.x;
    if (idx >= Nn * Nn) return;
    int j = idx % Nn;
    g_S[idx] /= g_rowsum[j];
}

// ---------------- pack x (B,N,C) -> X (N, B*C) ----------------
__global__ void k_pack(const float* __restrict__ x) {
    int idx = blockIdx.x * 256 + threadIdx.x;
    if (idx >= Nn * BC) return;
    int m = idx / BC, q = idx % BC;
    int b = q / Cc, c = q % Cc;
    g_X[idx] = x[((size_t)b * Nn + m) * Cc + c];
}

// ---------------- SGEMM: C = S @ B  (M=K=2000, Nc=272) ----------------
// BM=64 BN=64 BK=16, 256 threads, 4x4 microtile.
__global__ void k_sgemm(int mode) {
    const float* __restrict__ A  = g_S;
    const float* __restrict__ Bm = (mode == 0) ? g_X : g_R1;
    float* __restrict__ Cm       = (mode == 0) ? g_R1 : g_R2;
    constexpr int M = Nn, Kd = Nn, Nc = BC;

    __shared__ float As[16][64];
    __shared__ float Bs[16][64];
    int t  = threadIdx.x;
    int tx = t & 15, ty = t >> 4;
    int r0 = blockIdx.y * 64, n0 = blockIdx.x * 64;
    int arow = t >> 2, ac4 = (t & 3) * 4;
    int brow = t >> 4, bc4 = (t & 15) * 4;
    float acc[4][4] = {};

    for (int k0 = 0; k0 < Kd; k0 += 16) {
        float4 av = make_float4(0.f, 0.f, 0.f, 0.f);
        if (r0 + arow < M)
            av = *(const float4*)&A[(size_t)(r0 + arow) * Kd + k0 + ac4];
        As[ac4 + 0][arow] = av.x; As[ac4 + 1][arow] = av.y;
        As[ac4 + 2][arow] = av.z; As[ac4 + 3][arow] = av.w;

        float4 bv = make_float4(0.f, 0.f, 0.f, 0.f);
        int bc = n0 + bc4;
        if (bc + 3 < Nc) {
            bv = *(const float4*)&Bm[(size_t)(k0 + brow) * Nc + bc];
        } else {
            float tmp[4] = {0.f, 0.f, 0.f, 0.f};
            for (int q = 0; q < 4; q++)
                if (bc + q < Nc) tmp[q] = Bm[(size_t)(k0 + brow) * Nc + bc + q];
            bv = make_float4(tmp[0], tmp[1], tmp[2], tmp[3]);
        }
        *(float4*)&Bs[brow][bc4] = bv;
        __syncthreads();

        #pragma unroll
        for (int kk = 0; kk < 16; kk++) {
            float a[4], b[4];
            *(float4*)a = *(const float4*)&As[kk][ty * 4];
            *(float4*)b = *(const float4*)&Bs[kk][tx * 4];
            #pragma unroll
            for (int i = 0; i < 4; i++)
                #pragma unroll
                for (int j = 0; j < 4; j++)
                    acc[i][j] += a[i] * b[j];
        }
        __syncthreads();
    }
    #pragma unroll
    for (int i = 0; i < 4; i++) {
        int r = r0 + ty * 4 + i;
        if (r >= M) continue;
        #pragma unroll
        for (int j = 0; j < 4; j++) {
            int c = n0 + tx * 4 + j;
            if (c < Nc) Cm[(size_t)r * Nc + c] = acc[i][j];
        }
    }
}

// ---------------- node projections: out[n, c] = sum_d ne[n,d]*pool[d,c] ----------------
__global__ void k_proj(const float* __restrict__ ne, const float* __restrict__ pool,
                       int cols, int mode) {
    __shared__ float p_s[16][256];
    __shared__ float ne_s[16][17];
    int n0 = blockIdx.x * 16;
    int c0 = blockIdx.y * 256;
    int t = threadIdx.x;
    for (int d = 0; d < 16; d++)
        p_s[d][t] = (c0 + t < cols) ? pool[(size_t)d * cols + c0 + t] : 0.f;
    { int nn = t >> 4, d = t & 15; ne_s[nn][d] = (n0 + nn < Nn) ? ne[(n0 + nn) * 16 + d] : 0.f; }
    __syncthreads();
    int c = c0 + t;
    if (c >= cols) return;
    float* outp = (mode == 0) ? g_W : (mode == 1) ? g_bias : (mode == 2) ? g_wwt : g_wws;
    for (int nn = 0; nn < 16; nn++) {
        if (n0 + nn >= Nn) break;
        float acc = 0.f;
        #pragma unroll
        for (int d = 0; d < 16; d++) acc += ne_s[nn][d] * p_s[d][t];
        outp[(size_t)(n0 + nn) * cols + c] = acc;
    }
}

// ---------------- gnn_w row sums ----------------
__global__ void k_rs(const float* __restrict__ gnn_w) {
    __shared__ float red[256];
    int m = blockIdx.x, t = threadIdx.x;
    float s = 0.f;
    for (int j = t; j < Nn; j += 256) s += gnn_w[(size_t)m * Nn + j];
    red[t] = s; __syncthreads();
    for (int st = 128; st > 0; st >>= 1) { if (t < st) red[t] += red[t + st]; __syncthreads(); }
    if (t == 0) g_rs[m] = red[0];
}

// ---------------- U,V from bootstrap-gathered xe (with Linear(1,1)) ----------------
__global__ void k_uv(const float* __restrict__ xew, const int* __restrict__ bidx,
                     const float* __restrict__ lw, const float* __restrict__ lb) {
    int idx = blockIdx.x * 256 + threadIdx.x;
    if (idx >= Bb * Ee) return;
    int b = idx / Ee, i = idx % Ee;
    float w = lw[0], bia = lb[0];
    float u = 0.f, v = 0.f;
    #pragma unroll
    for (int f = 0; f < NBt; f++) {
        int tt = bidx[f]; tt = max(0, min(Ww - 1, tt));
        float xv = xew[((size_t)(b * Ww + tt)) * Ee + i] * w + bia;
        u += xv; v += (float)(NBt - 1 - f) * xv;
    }
    g_U[idx] = u; g_V[idx] = v;
}

// ---------------- hodge GEMM partials: Hpart[ch,b,j] = sum_{i in chunk} U[b,i]*hodge[i,j] ----------------
__global__ void k_hodge(const float* __restrict__ hodge) {
    __shared__ float u_s[16][192];
    constexpr int CL = (Ee + HCH - 1) / HCH; // 188
    int ch = blockIdx.y;
    int i0 = ch * CL;
    int ilen = min(CL, Ee - i0);
    int t = threadIdx.x;
    for (int idx = t; idx < Bb * ilen; idx += 256) {
        int bb = idx / ilen, ii = idx % ilen;
        u_s[bb][ii] = g_U[bb * Ee + i0 + ii];
    }
    __syncthreads();
    int j = blockIdx.x * 256 + t;
    if (j >= Ee) return;
    float acc[16];
    #pragma unroll
    for (int bb = 0; bb < 16; bb++) acc[bb] = 0.f;
    for (int ii = 0; ii < ilen; ii++) {
        float h = hodge[(size_t)(i0 + ii) * Ee + j];
        #pragma unroll
        for (int bb = 0; bb < 16; bb++) acc[bb] += u_s[bb][ii] * h;
    }
    #pragma unroll
    for (int bb = 0; bb < 16; bb++)
        g_Hpart[((size_t)ch * Bb + bb) * Ee + j] = acc[bb];
}

// ---------------- Ybar = (sum_ch Hpart + jump*V) / NB ----------------
__global__ void k_ybar(const void* p_jump) {
    int idx = blockIdx.x * 256 + threadIdx.x;
    if (idx >= Bb * Ee) return;
    int b = idx / Ee, j = idx % Ee;
    float jump = scalar_val(p_jump);
    float s = jump * g_V[idx];
    #pragma unroll
    for (int ch = 0; ch < HCH; ch++) s += g_Hpart[((size_t)ch * Bb + b) * Ee + j];
    g_Ybar[idx] = s * (1.f / (float)NBt);
}

// ---------------- Mpart[sp,b,n] = sum_{e in split} Ybar[b,e]*inc[n,e] ----------------
__global__ void k_m(const float* __restrict__ inc) {
    __shared__ float inc_s[32][65];
    __shared__ float yb_s[16][64];
    constexpr int SL = Ee / MKS; // 750
    int n0 = blockIdx.x * 32;
    int sp = blockIdx.y;
    int e_start = sp * SL, e_end = e_start + SL;
    int t = threadIdx.x;
    int nl = t & 31, bg = t >> 5;
    int b0 = bg * 2, b1 = bg * 2 + 1;
    float acc0 = 0.f, acc1 = 0.f;
    for (int e0 = e_start; e0 < e_end; e0 += 64) {
        for (int idx = t; idx < 32 * 64; idx += 256) {
            int r = idx >> 6, c = idx & 63;
            int n = n0 + r, e = e0 + c;
            inc_s[r][c] = (n < Nn && e < e_end) ? inc[(size_t)n * Ee + e] : 0.f;
        }
        for (int idx = t; idx < 16 * 64; idx += 256) {
            int bb = idx >> 6, c = idx & 63;
            int e = e0 + c;
            yb_s[bb][c] = (e < e_end) ? g_Ybar[bb * Ee + e] : 0.f;
        }
        __syncthreads();
        #pragma unroll
        for (int c = 0; c < 64; c++) {
            float w = inc_s[nl][c];
            acc0 += yb_s[b0][c] * w;
            acc1 += yb_s[b1][c] * w;
        }
        __syncthreads();
    }
    int n = n0 + nl;
    if (n < Nn) {
        g_Mpart[((size_t)sp * Bb + b0) * Nn + n] = acc0;
        g_Mpart[((size_t)sp * Bb + b1) * Nn + n] = acc1;
    }
}

// ---------------- XW[b,n] = sum_t x_window[b,t,n]*Tp[t] ----------------
__global__ void k_xw(const float* __restrict__ xwin, const float* __restrict__ Tp) {
    int idx = blockIdx.x * 256 + threadIdx.x;
    if (idx >= Bb * Nn) return;
    int b = idx / Nn, n = idx % Nn;
    float s = 0.f;
    #pragma unroll
    for (int t = 0; t < Ww; t++) s += xwin[((size_t)(b * Ww + t)) * Nn + n] * Tp[t];
    g_XW[idx] = s;
}

// ---------------- final fused assembly: concat 4 branches + bias ----------------
__global__ void k_assembly(const float* __restrict__ zfc_in, const float* __restrict__ gnn_b,
                           float* __restrict__ out) {
    __shared__ float xs_s[16][52];
    __shared__ float zfc_s[16][32];
    __shared__ float xw_s[16];
    __shared__ float m_s[16];
    int n = blockIdx.x;
    int t = threadIdx.x;
    for (int idx = t; idx < Bb * KC; idx += 256) {   // 816 values
        int b = idx / KC, ki = idx % KC;
        int k = ki / Cc, c = ki % Cc;
        const float* src = (k == 0) ? g_X : (k == 1) ? g_R1 : g_R2;
        xs_s[b][ki] = src[(size_t)n * BC + b * Cc + c];
    }
    for (int idx = t; idx < Bb * 32; idx += 256)
        zfc_s[idx >> 5][idx & 31] = zfc_in[idx];
    if (t < 16) {
        xw_s[t] = g_XW[t * Nn + n];
        float ms = 0.f;
        #pragma unroll
        for (int sp = 0; sp < MKS; sp++) ms += g_Mpart[((size_t)sp * Bb + t) * Nn + n];
        m_s[t] = ms;
    }
    __syncthreads();

    int o = t;
    float biasv = g_bias[(size_t)n * Oo + o];
    if (o < 64) {                       // graph diffusion branch
        float w[KC];
        #pragma unroll
        for (int ki = 0; ki < KC; ki++) w[ki] = g_W[(size_t)n * WCOLS + ki * 64 + o];
        for (int b = 0; b < 16; b++) {
            float acc = 0.f;
            #pragma unroll
            for (int ki = 0; ki < KC; ki++) acc += xs_s[b][ki] * w[ki];
            out[((size_t)b * Nn + n) * Oo + o] = acc + biasv;
        }
    } else if (o < 96) {                // ZFC branch (reshape-aware)
        int c = o - 64;
        int flat = n * 32 + c;
        int r = flat / Nn;
        int m = flat - r * Nn;
        float rsv = g_rs[m], gb = gnn_b[m];
        for (int b = 0; b < 16; b++) {
            float v = fmaxf(zfc_s[b][r] * rsv + gb, 0.f);
            out[((size_t)b * Nn + n) * Oo + o] = v + biasv;
        }
    } else if (o < 224) {               // temporal branch
        float wv = g_wwt[(size_t)n * 128 + (o - 96)];
        for (int b = 0; b < 16; b++)
            out[((size_t)b * Nn + n) * Oo + o] = xw_s[b] * wv + biasv;
    } else {                            // supra / hypergraph branch
        float wv = g_wws[(size_t)n * 32 + (o - 224)];
        for (int b = 0; b < 16; b++)
            out[((size_t)b * Nn + n) * Oo + o] = m_s[b] * wv + biasv;
    }
}

// ---------------- host launch ----------------
extern "C" void kernel_launch(void* const* d_in, const int* in_sizes, int n_in,
                              void* d_out, int out_size) {
    const float* x     = (const float*)d_in[0];
    const float* xwin  = (const float*)d_in[1];
    const float* ne    = (const float*)d_in[2];
    const void*  p_fix = d_in[3];
    const float* adj   = (const float*)d_in[4];
    const void*  p_sty = d_in[5];
    const void*  p_jmp = d_in[6];
    const float* zfc   = (const float*)d_in[7];
    const float* hodge = (const float*)d_in[8];
    const float* xew   = (const float*)d_in[9];
    const float* inc   = (const float*)d_in[10];
    const float* wp    = (const float*)d_in[11];
    const float* wws_p = (const float*)d_in[12];
    const float* wwt_p = (const float*)d_in[13];
    const float* bp    = (const float*)d_in[14];
    const float* Tp    = (const float*)d_in[15];
    const float* lw    = (const float*)d_in[16];
    const float* lb    = (const float*)d_in[17];
    const float* gnn_w = (const float*)d_in[18];
    const float* gnn_b = (const float*)d_in[19];
    const int*   bidx  = (const int*)d_in[20];
    float* out = (float*)d_out;

    // S construction
    k_s0<<<dim3(125, 125), 256>>>(ne, p_sty);
    k_softmax<<<Nn, 256>>>(p_fix, adj);
    k_colscale<<<(Nn * Nn + 255) / 256, 256>>>();

    // diffusion supports
    k_pack<<<(Nn * BC + 255) / 256, 256>>>(x);
    k_sgemm<<<dim3(5, 32), 256>>>(0);  // R1 = S @ X
    k_sgemm<<<dim3(5, 32), 256>>>(1);  // R2 = S @ R1

    // node projections
    k_proj<<<dim3(125, 13), 256>>>(ne, wp, WCOLS, 0);
    k_proj<<<dim3(125, 1), 256>>>(ne, bp, Oo, 1);
    k_proj<<<dim3(125, 1), 256>>>(ne, wwt_p, 128, 2);
    k_proj<<<dim3(125, 1), 256>>>(ne, wws_p, 32, 3);

    // ZFC rowsums
    k_rs<<<Nn, 256>>>(gnn_w);

    // supra branch
    k_uv<<<(Bb * Ee + 255) / 256, 256>>>(xew, bidx, lw, lb);
    k_hodge<<<dim3((Ee + 255) / 256, HCH), 256>>>(hodge);
    k_ybar<<<(Bb * Ee + 255) / 256, 256>>>(p_jmp);
    k_m<<<dim3((Nn + 31) / 32, MKS), 256>>>(inc);

    // temporal branch
    k_xw<<<(Bb * Nn + 255) / 256, 256>>>(xwin, Tp);

    // fused output
    k_assembly<<<Nn, 256>>>(zfc, gnn_b, out);
}

// round 2
// speedup vs baseline: 1.5375x; 1.5375x over previous
#include <cuda_runtime.h>
#include <cuda_bf16.h>
#include <math.h>

typedef unsigned short ushortT;
typedef unsigned int uintT;

// ---------------- problem dims ----------------
constexpr int Bb = 16, Nn = 2000, Ee = 3000, Cc = 17, Ww = 12, Dd = 16, Oo = 256, Kk = 3, NBt = 3;
constexpr int BCP   = 288;           // padded packed columns (272 valid)
constexpr int KC    = Kk * Cc;       // 51
constexpr int WCOLS = KC * 64;       // 3264
constexpr int HCH   = 16;            // hodge K-split chunks
constexpr int MKS   = 4;             // inc GEMM K-splits

// ---------------- scratch (device globals, no allocation) ----------------
__device__ __align__(16) float  g_S[Nn * Nn];
__device__ __align__(16) float  g_cinv[Nn];
__device__ __align__(16) ushortT g_Sh[Nn * Nn];
__device__ __align__(16) ushortT g_Sl[Nn * Nn];
__device__ __align__(16) ushortT g_Xh[Nn * BCP];
__device__ __align__(16) ushortT g_Xl[Nn * BCP];
__device__ __align__(16) ushortT g_R1h[Nn * BCP];
__device__ __align__(16) ushortT g_R1l[Nn * BCP];
__device__ __align__(16) float  g_R1[Nn * BCP];
__device__ __align__(16) float  g_R2[Nn * BCP];
__device__ float g_W   [Nn * WCOLS];
__device__ float g_bias[Nn * Oo];
__device__ float g_wwt [Nn * 128];
__device__ float g_wws [Nn * 32];
__device__ float g_U[Bb * Ee];
__device__ float g_V[Bb * Ee];
__device__ float g_Hpart[HCH * Bb * Ee];
__device__ float g_Ybar[Bb * Ee];
__device__ float g_Mpart[MKS * Bb * Nn];
__device__ float g_XW[Bb * Nn];
__device__ float g_rs[Nn];

__device__ __forceinline__ float scalar_val(const void* p) {
    int v = *(const int*)p;
    if (v > -100000000 && v < 100000000) return (float)v;
    return __int_as_float(v);
}
__device__ __forceinline__ ushortT f2bf(float v) {
    __nv_bfloat16 b = __float2bfloat16(v);
    return *reinterpret_cast<ushortT*>(&b);
}
__device__ __forceinline__ float bf2f(ushortT u) {
    __nv_bfloat16 b; *reinterpret_cast<ushortT*>(&b) = u;
    return __bfloat162float(b);
}

// ---------------- S0 = relu(ne @ ne^T), diag = stay ----------------
__global__ void k_s0(const float* __restrict__ ne, const void* p_stay) {
    __shared__ float a_s[16][17], b_s[16][17];
    int i0 = blockIdx.y * 16, j0 = blockIdx.x * 16;
    int t = threadIdx.x;
    int r = t >> 4, d = t & 15;
    a_s[r][d] = (i0 + r < Nn) ? ne[(i0 + r) * Dd + d] : 0.f;
    b_s[r][d] = (j0 + r < Nn) ? ne[(j0 + r) * Dd + d] : 0.f;
    __syncthreads();
    int ty = t >> 4, tx = t & 15;
    int i = i0 + ty, j = j0 + tx;
    if (i < Nn && j < Nn) {
        float acc = 0.f;
        #pragma unroll
        for (int dd = 0; dd < 16; dd++) acc += a_s[ty][dd] * b_s[tx][dd];
        acc = fmaxf(acc, 0.f);
        if (i == j) acc = scalar_val(p_stay);
        g_S[(size_t)i * Nn + j] = acc;
    }
}

// ---------------- row softmax (or adj*exp) + column-scale reciprocals ----------------
__global__ void k_softmax(const void* p_fixed, const float* __restrict__ adj) {
    __shared__ float row[Nn];
    __shared__ float red[256];
    int i = blockIdx.x, t = threadIdx.x;
    bool fixed = (scalar_val(p_fixed) != 0.f);
    for (int j = t; j < Nn; j += 256) row[j] = g_S[(size_t)i * Nn + j];
    __syncthreads();
    float outsum;
    if (!fixed) {
        float m = -1e30f;
        for (int j = t; j < Nn; j += 256) m = fmaxf(m, row[j]);
        red[t] = m; __syncthreads();
        for (int s = 128; s > 0; s >>= 1) { if (t < s) red[t] = fmaxf(red[t], red[t + s]); __syncthreads(); }
        m = red[0]; __syncthreads();
        float s = 0.f;
        for (int j = t; j < Nn; j += 256) { float e = expf(row[j] - m); row[j] = e; s += e; }
        red[t] = s; __syncthreads();
        for (int st = 128; st > 0; st >>= 1) { if (t < st) red[t] += red[t + st]; __syncthreads(); }
        float inv = 1.f / red[0]; __syncthreads();
        float fs = 0.f;
        for (int j = t; j < Nn; j += 256) {
            float v = row[j] * inv;
            g_S[(size_t)i * Nn + j] = v;
            fs += v;
        }
        red[t] = fs; __syncthreads();
        for (int st = 128; st > 0; st >>= 1) { if (t < st) red[t] += red[t + st]; __syncthreads(); }
        outsum = red[0];
    } else {
        float fs = 0.f;
        for (int j = t; j < Nn; j += 256) {
            float v = adj[(size_t)i * Nn + j] * expf(row[j]);
            g_S[(size_t)i * Nn + j] = v;
            fs += v;
        }
        red[t] = fs; __syncthreads();
        for (int st = 128; st > 0; st >>= 1) { if (t < st) red[t] += red[t + st]; __syncthreads(); }
        outsum = red[0];
    }
    if (t == 0) g_cinv[i] = 1.f / outsum;
}

// ---------------- S split to bf16 hi/lo with column scale folded in ----------------
__global__ void k_splitS() {
    int i4 = blockIdx.x * 256 + threadIdx.x;
    if (i4 >= Nn * Nn / 4) return;
    int j = (i4 * 4) % Nn;
    float4 s  = ((const float4*)g_S)[i4];
    float4 ci = *(const float4*)&g_cinv[j];
    float v[4] = { s.x * ci.x, s.y * ci.y, s.z * ci.z, s.w * ci.w };
    ushort4 hh, ll;
    ushortT* hp = &hh.x; ushortT* lp = &ll.x;
    #pragma unroll
    for (int q = 0; q < 4; q++) {
        ushortT h = f2bf(v[q]);
        hp[q] = h;
        lp[q] = f2bf(v[q] - bf2f(h));
    }
    ((ushort4*)g_Sh)[i4] = hh;
    ((ushort4*)g_Sl)[i4] = ll;
}

// ---------------- x (B,N,C) -> bf16 hi/lo packed [m][288] ----------------
__global__ void k_splitX(const float* __restrict__ x) {
    int idx = blockIdx.x * 256 + threadIdx.x;
    if (idx >= Nn * BCP) return;
    int m = idx / BCP, q = idx % BCP;
    float v = 0.f;
    if (q < Bb * Cc) {
        int b = q / Cc, c = q % Cc;
        v = x[((size_t)b * Nn + m) * Cc + c];
    }
    ushortT h = f2bf(v);
    g_Xh[idx] = h;
    g_Xl[idx] = f2bf(v - bf2f(h));
}

// ---------------- R1 fp32 -> bf16 hi/lo ----------------
__global__ void k_splitR1() {
    int i4 = blockIdx.x * 256 + threadIdx.x;
    if (i4 >= Nn * BCP / 4) return;
    float4 s = ((const float4*)g_R1)[i4];
    float v[4] = { s.x, s.y, s.z, s.w };
    ushort4 hh, ll;
    ushortT* hp = &hh.x; ushortT* lp = &ll.x;
    #pragma unroll
    for (int q = 0; q < 4; q++) {
        ushortT h = f2bf(v[q]);
        hp[q] = h;
        lp[q] = f2bf(v[q] - bf2f(h));
    }
    ((ushort4*)g_R1h)[i4] = hh;
    ((ushort4*)g_R1l)[i4] = ll;
}

// ---------------- tensor-core GEMM: C[2000,288] = A[2000,2000] @ B[2000,288] ----------------
// bf16x3 compensated: C = Ah*Bh + Ah*Bl + Al*Bh, fp32 accum.
__device__ __forceinline__ void ldsm_x4(uintT* r, uintT addr) {
    asm volatile("ldmatrix.sync.aligned.m8n8.x4.shared.b16 {%0,%1,%2,%3}, [%4];"
                 : "=r"(r[0]), "=r"(r[1]), "=r"(r[2]), "=r"(r[3]) : "r"(addr));
}
__device__ __forceinline__ void ldsm_x2t(uintT* r, uintT addr) {
    asm volatile("ldmatrix.sync.aligned.m8n8.x2.trans.shared.b16 {%0,%1}, [%2];"
                 : "=r"(r[0]), "=r"(r[1]) : "r"(addr));
}
__device__ __forceinline__ void mma16816(float* c, const uintT* a, const uintT* b) {
    asm volatile("mma.sync.aligned.m16n8k16.row.col.f32.bf16.bf16.f32 "
                 "{%0,%1,%2,%3}, {%4,%5,%6,%7}, {%8,%9}, {%0,%1,%2,%3};"
                 : "+f"(c[0]), "+f"(c[1]), "+f"(c[2]), "+f"(c[3])
                 : "r"(a[0]), "r"(a[1]), "r"(a[2]), "r"(a[3]), "r"(b[0]), "r"(b[1]));
}

__global__ void __launch_bounds__(128) k_mmagemm(
        const ushortT* __restrict__ Ah, const ushortT* __restrict__ Al,
        const ushortT* __restrict__ Bh, const ushortT* __restrict__ Bl,
        float* __restrict__ Cm) {
    constexpr int ASTR = 24;  // bf16 units per A smem row (16 + 8 pad)
    constexpr int BSTR = 56;  // bf16 units per B smem row (48 + 8 pad)
    __shared__ ushortT sAh[2][64 * ASTR], sAl[2][64 * ASTR];
    __shared__ ushortT sBh[2][16 * BSTR], sBl[2][16 * BSTR];

    int t = threadIdx.x;
    int warp = t >> 5, lane = t & 31;
    int wm = (warp >> 1) * 32, wn = (warp & 1) * 24;
    int bm0 = blockIdx.y * 64, bn0 = blockIdx.x * 48;

    int ar = t >> 1, ak = (t & 1) * 8;   // A: row 0..63, k-half 0/8
    int br = t / 6,  bs = t % 6;         // B: k-row 0..15, 8-col seg (valid t<96)
    bool bact = t < 96;

    float acc[2][3][4];
    #pragma unroll
    for (int i = 0; i < 2; i++)
        #pragma unroll
        for (int j = 0; j < 3; j++)
            #pragma unroll
            for (int q = 0; q < 4; q++) acc[i][j][q] = 0.f;

    uint4 pAh, pAl, pBh, pBl;
    pBh = make_uint4(0,0,0,0); pBl = pBh;

    // prologue load kb=0
    {
        int gr = bm0 + ar;
        if (gr < Nn) {
            size_t off = (size_t)gr * Nn + ak;
            pAh = *(const uint4*)(Ah + off);
            pAl = *(const uint4*)(Al + off);
        } else { pAh = make_uint4(0,0,0,0); pAl = pAh; }
        if (bact) {
            size_t off = (size_t)br * BCP + bn0 + bs * 8;
            pBh = *(const uint4*)(Bh + off);
            pBl = *(const uint4*)(Bl + off);
        }
        *(uint4*)&sAh[0][ar * ASTR + ak] = pAh;
        *(uint4*)&sAl[0][ar * ASTR + ak] = pAl;
        if (bact) {
            *(uint4*)&sBh[0][br * BSTR + bs * 8] = pBh;
            *(uint4*)&sBl[0][br * BSTR + bs * 8] = pBl;
        }
    }
    __syncthreads();

    uintT aoff = ((wm + (lane & 15)) * ASTR + ((lane & 16) ? 8 : 0)) * 2;
    uintT boff = ((lane & 15) * BSTR + wn) * 2;
    uintT baseAh0 = (uintT)__cvta_generic_to_shared(&sAh[0][0]);
    uintT baseAl0 = (uintT)__cvta_generic_to_shared(&sAl[0][0]);
    uintT baseBh0 = (uintT)__cvta_generic_to_shared(&sBh[0][0]);
    uintT baseBl0 = (uintT)__cvta_generic_to_shared(&sBl[0][0]);
    constexpr uintT abufB = 64 * ASTR * 2;
    constexpr uintT bbufB = 16 * BSTR * 2;

    constexpr int NKB = Nn / 16;  // 125
    for (int kb = 0; kb < NKB; kb++) {
        int cur = kb & 1;
        if (kb < NKB - 1) {  // prefetch next tile into regs
            int gr = bm0 + ar;
            if (gr < Nn) {
                size_t off = (size_t)gr * Nn + (kb + 1) * 16 + ak;
                pAh = *(const uint4*)(Ah + off);
                pAl = *(const uint4*)(Al + off);
            } else { pAh = make_uint4(0,0,0,0); pAl = pAh; }
            if (bact) {
                size_t off = (size_t)((kb + 1) * 16 + br) * BCP + bn0 + bs * 8;
                pBh = *(const uint4*)(Bh + off);
                pBl = *(const uint4*)(Bl + off);
            }
        }
        uintT fah[2][4], fal[2][4], fbh[3][2], fbl[3][2];
        #pragma unroll
        for (int mt = 0; mt < 2; mt++) {
            ldsm_x4(fah[mt], baseAh0 + cur * abufB + aoff + mt * 16 * ASTR * 2);
            ldsm_x4(fal[mt], baseAl0 + cur * abufB + aoff + mt * 16 * ASTR * 2);
        }
        #pragma unroll
        for (int nt = 0; nt < 3; nt++) {
            ldsm_x2t(fbh[nt], baseBh0 + cur * bbufB + boff + nt * 16);
            ldsm_x2t(fbl[nt], baseBl0 + cur * bbufB + boff + nt * 16);
        }
        #pragma unroll
        for (int mt = 0; mt < 2; mt++)
            #pragma unroll
            for (int nt = 0; nt < 3; nt++) {
                mma16816(acc[mt][nt], fah[mt], fbh[nt]);
                mma16816(acc[mt][nt], fah[mt], fbl[nt]);
                mma16816(acc[mt][nt], fal[mt], fbh[nt]);
            }
        __syncthreads();
        if (kb < NKB - 1) {
            int nxt = cur ^ 1;
            *(uint4*)&sAh[nxt][ar * ASTR + ak] = pAh;
            *(uint4*)&sAl[nxt][ar * ASTR + ak] = pAl;
            if (bact) {
                *(uint4*)&sBh[nxt][br * BSTR + bs * 8] = pBh;
                *(uint4*)&sBl[nxt][br * BSTR + bs * 8] = pBl;
            }
            __syncthreads();
        }
    }
    // epilogue
    #pragma unroll
    for (int mt = 0; mt < 2; mt++)
        #pragma unroll
        for (int nt = 0; nt < 3; nt++) {
            int row = bm0 + wm + mt * 16 + (lane >> 2);
            int col = bn0 + wn + nt * 8 + (lane & 3) * 2;
            if (row < Nn)
                *(float2*)&Cm[(size_t)row * BCP + col] = make_float2(acc[mt][nt][0], acc[mt][nt][1]);
            if (row + 8 < Nn)
                *(float2*)&Cm[(size_t)(row + 8) * BCP + col] = make_float2(acc[mt][nt][2], acc[mt][nt][3]);
        }
}

// ---------------- node projections ----------------
__global__ void k_proj(const float* __restrict__ ne, const float* __restrict__ pool,
                       int cols, int mode) {
    __shared__ float p_s[16][256];
    __shared__ float ne_s[16][17];
    int n0 = blockIdx.x * 16;
    int c0 = blockIdx.y * 256;
    int t = threadIdx.x;
    for (int d = 0; d < 16; d++)
        p_s[d][t] = (c0 + t < cols) ? pool[(size_t)d * cols + c0 + t] : 0.f;
    { int nn = t >> 4, d = t & 15; ne_s[nn][d] = (n0 + nn < Nn) ? ne[(n0 + nn) * 16 + d] : 0.f; }
    __syncthreads();
    int c = c0 + t;
    if (c >= cols) return;
    float* outp = (mode == 0) ? g_W : (mode == 1) ? g_bias : (mode == 2) ? g_wwt : g_wws;
    for (int nn = 0; nn < 16; nn++) {
        if (n0 + nn >= Nn) break;
        float acc = 0.f;
        #pragma unroll
        for (int d = 0; d < 16; d++) acc += ne_s[nn][d] * p_s[d][t];
        outp[(size_t)(n0 + nn) * cols + c] = acc;
    }
}

// ---------------- gnn_w row sums ----------------
__global__ void k_rs(const float* __restrict__ gnn_w) {
    __shared__ float red[256];
    int m = blockIdx.x, t = threadIdx.x;
    float s = 0.f;
    for (int j = t; j < Nn; j += 256) s += gnn_w[(size_t)m * Nn + j];
    red[t] = s; __syncthreads();
    for (int st = 128; st > 0; st >>= 1) { if (t < st) red[t] += red[t + st]; __syncthreads(); }
    if (t == 0) g_rs[m] = red[0];
}

// ---------------- U,V from bootstrap-gathered xe ----------------
__global__ void k_uv(const float* __restrict__ xew, const int* __restrict__ bidx,
                     const float* __restrict__ lw, const float* __restrict__ lb) {
    int idx = blockIdx.x * 256 + threadIdx.x;
    if (idx >= Bb * Ee) return;
    int b = idx / Ee, i = idx % Ee;
    float w = lw[0], bia = lb[0];
    float u = 0.f, v = 0.f;
    #pragma unroll
    for (int f = 0; f < NBt; f++) {
        int tt = bidx[f]; tt = max(0, min(Ww - 1, tt));
        float xv = xew[((size_t)(b * Ww + tt)) * Ee + i] * w + bia;
        u += xv; v += (float)(NBt - 1 - f) * xv;
    }
    g_U[idx] = u; g_V[idx] = v;
}

// ---------------- hodge partials ----------------
__global__ void k_hodge(const float* __restrict__ hodge) {
    __shared__ float u_s[16][192];
    constexpr int CL = (Ee + HCH - 1) / HCH; // 188
    int ch = blockIdx.y;
    int i0 = ch * CL;
    int ilen = min(CL, Ee - i0);
    int t = threadIdx.x;
    for (int idx = t; idx < Bb * ilen; idx += 256) {
        int bb = idx / ilen, ii = idx % ilen;
        u_s[bb][ii] = g_U[bb * Ee + i0 + ii];
    }
    __syncthreads();
    int j = blockIdx.x * 256 + t;
    if (j >= Ee) return;
    float acc[16];
    #pragma unroll
    for (int bb = 0; bb < 16; bb++) acc[bb] = 0.f;
    for (int ii = 0; ii < ilen; ii++) {
        float h = hodge[(size_t)(i0 + ii) * Ee + j];
        #pragma unroll
        for (int bb = 0; bb < 16; bb++) acc[bb] += u_s[bb][ii] * h;
    }
    #pragma unroll
    for (int bb = 0; bb < 16; bb++)
        g_Hpart[((size_t)ch * Bb + bb) * Ee + j] = acc[bb];
}

__global__ void k_ybar(const void* p_jump) {
    int idx = blockIdx.x * 256 + threadIdx.x;
    if (idx >= Bb * Ee) return;
    int b = idx / Ee, j = idx % Ee;
    float jump = scalar_val(p_jump);
    float s = jump * g_V[idx];
    #pragma unroll
    for (int ch = 0; ch < HCH; ch++) s += g_Hpart[((size_t)ch * Bb + b) * Ee + j];
    g_Ybar[idx] = s * (1.f / (float)NBt);
}

// ---------------- Mpart[sp,b,n] = sum_{e in split} Ybar[b,e]*inc[n,e] ----------------
__global__ void k_m(const float* __restrict__ inc) {
    __shared__ float inc_s[32][65];
    __shared__ float yb_s[16][64];
    constexpr int SL = Ee / MKS; // 750
    int n0 = blockIdx.x * 32;
    int sp = blockIdx.y;
    int e_start = sp * SL, e_end = e_start + SL;
    int t = threadIdx.x;
    int nl = t & 31, bg = t >> 5;
    int b0 = bg * 2, b1 = bg * 2 + 1;
    float acc0 = 0.f, acc1 = 0.f;
    for (int e0 = e_start; e0 < e_end; e0 += 64) {
        for (int idx = t; idx < 32 * 64; idx += 256) {
            int r = idx >> 6, c = idx & 63;
            int n = n0 + r, e = e0 + c;
            inc_s[r][c] = (n < Nn && e < e_end) ? inc[(size_t)n * Ee + e] : 0.f;
        }
        for (int idx = t; idx < 16 * 64; idx += 256) {
            int bb = idx >> 6, c = idx & 63;
            int e = e0 + c;
            yb_s[bb][c] = (e < e_end) ? g_Ybar[bb * Ee + e] : 0.f;
        }
        __syncthreads();
        #pragma unroll
        for (int c = 0; c < 64; c++) {
            float w = inc_s[nl][c];
            acc0 += yb_s[b0][c] * w;
            acc1 += yb_s[b1][c] * w;
        }
        __syncthreads();
    }
    int n = n0 + nl;
    if (n < Nn) {
        g_Mpart[((size_t)sp * Bb + b0) * Nn + n] = acc0;
        g_Mpart[((size_t)sp * Bb + b1) * Nn + n] = acc1;
    }
}

// ---------------- XW[b,n] = sum_t x_window[b,t,n]*Tp[t] ----------------
__global__ void k_xw(const float* __restrict__ xwin, const float* __restrict__ Tp) {
    int idx = blockIdx.x * 256 + threadIdx.x;
    if (idx >= Bb * Nn) return;
    int b = idx / Nn, n = idx % Nn;
    float s = 0.f;
    #pragma unroll
    for (int t = 0; t < Ww; t++) s += xwin[((size_t)(b * Ww + t)) * Nn + n] * Tp[t];
    g_XW[idx] = s;
}

// ---------------- fused assembly ----------------
__global__ void k_assembly(const float* __restrict__ x, const float* __restrict__ zfc_in,
                           const float* __restrict__ gnn_b, float* __restrict__ out) {
    __shared__ float xs_s[16][52];
    __shared__ float zfc_s[16][32];
    __shared__ float xw_s[16];
    __shared__ float m_s[16];
    int n = blockIdx.x;
    int t = threadIdx.x;
    for (int idx = t; idx < Bb * KC; idx += 256) {   // 816 values
        int b = idx / KC, ki = idx % KC;
        int k = ki / Cc, c = ki % Cc;
        float v;
        if (k == 0)      v = x[((size_t)b * Nn + n) * Cc + c];
        else if (k == 1) v = g_R1[(size_t)n * BCP + b * Cc + c];
        else             v = g_R2[(size_t)n * BCP + b * Cc + c];
        xs_s[b][ki] = v;
    }
    for (int idx = t; idx < Bb * 32; idx += 256)
        zfc_s[idx >> 5][idx & 31] = zfc_in[idx];
    if (t < 16) {
        xw_s[t] = g_XW[t * Nn + n];
        float ms = 0.f;
        #pragma unroll
        for (int sp = 0; sp < MKS; sp++) ms += g_Mpart[((size_t)sp * Bb + t) * Nn + n];
        m_s[t] = ms;
    }
    __syncthreads();

    int o = t;
    float biasv = g_bias[(size_t)n * Oo + o];
    if (o < 64) {                       // graph diffusion branch
        float w[KC];
        #pragma unroll
        for (int ki = 0; ki < KC; ki++) w[ki] = g_W[(size_t)n * WCOLS + ki * 64 + o];
        for (int b = 0; b < 16; b++) {
            float acc = 0.f;
            #pragma unroll
            for (int ki = 0; ki < KC; ki++) acc += xs_s[b][ki] * w[ki];
            out[((size_t)b * Nn + n) * Oo + o] = acc + biasv;
        }
    } else if (o < 96) {                // ZFC branch (reshape-aware)
        int c = o - 64;
        int flat = n * 32 + c;
        int r = flat / Nn;
        int m = flat - r * Nn;
        float rsv = g_rs[m], gb = gnn_b[m];
        for (int b = 0; b < 16; b++) {
            float v = fmaxf(zfc_s[b][r] * rsv + gb, 0.f);
            out[((size_t)b * Nn + n) * Oo + o] = v + biasv;
        }
    } else if (o < 224) {               // temporal branch
        float wv = g_wwt[(size_t)n * 128 + (o - 96)];
        for (int b = 0; b < 16; b++)
            out[((size_t)b * Nn + n) * Oo + o] = xw_s[b] * wv + biasv;
    } else {                            // supra / hypergraph branch
        float wv = g_wws[(size_t)n * 32 + (o - 224)];
        for (int b = 0; b < 16; b++)
            out[((size_t)b * Nn + n) * Oo + o] = m_s[b] * wv + biasv;
    }
}

// ---------------- host launch ----------------
extern "C" void kernel_launch(void* const* d_in, const int* in_sizes, int n_in,
                              void* d_out, int out_size) {
    const float* x     = (const float*)d_in[0];
    const float* xwin  = (const float*)d_in[1];
    const float* ne    = (const float*)d_in[2];
    const void*  p_fix = d_in[3];
    const float* adj   = (const float*)d_in[4];
    const void*  p_sty = d_in[5];
    const void*  p_jmp = d_in[6];
    const float* zfc   = (const float*)d_in[7];
    const float* hodge = (const float*)d_in[8];
    const float* xew   = (const float*)d_in[9];
    const float* inc   = (const float*)d_in[10];
    const float* wp    = (const float*)d_in[11];
    const float* wws_p = (const float*)d_in[12];
    const float* wwt_p = (const float*)d_in[13];
    const float* bp    = (const float*)d_in[14];
    const float* Tp    = (const float*)d_in[15];
    const float* lw    = (const float*)d_in[16];
    const float* lb    = (const float*)d_in[17];
    const float* gnn_w = (const float*)d_in[18];
    const float* gnn_b = (const float*)d_in[19];
    const int*   bidx  = (const int*)d_in[20];
    float* out = (float*)d_out;

    // resolve device-global symbol addresses (host side, graph-capturable: no alloc)
    static ushortT *pSh = nullptr, *pSl, *pXh, *pXl, *pR1h, *pR1l;
    static float *pR1, *pR2;
    if (!pSh) {
        cudaGetSymbolAddress((void**)&pSh,  g_Sh);
        cudaGetSymbolAddress((void**)&pSl,  g_Sl);
        cudaGetSymbolAddress((void**)&pXh,  g_Xh);
        cudaGetSymbolAddress((void**)&pXl,  g_Xl);
        cudaGetSymbolAddress((void**)&pR1h, g_R1h);
        cudaGetSymbolAddress((void**)&pR1l, g_R1l);
        cudaGetSymbolAddress((void**)&pR1,  g_R1);
        cudaGetSymbolAddress((void**)&pR2,  g_R2);
    }

    // S construction
    k_s0<<<dim3(125, 125), 256>>>(ne, p_sty);
    k_softmax<<<Nn, 256>>>(p_fix, adj);
    k_splitS<<<(Nn * Nn / 4 + 255) / 256, 256>>>();

    // diffusion supports via tensor cores
    k_splitX<<<(Nn * BCP + 255) / 256, 256>>>(x);
    k_mmagemm<<<dim3(6, 32), 128>>>(pSh, pSl, pXh, pXl, pR1);   // R1 = S @ X
    k_splitR1<<<(Nn * BCP / 4 + 255) / 256, 256>>>();
    k_mmagemm<<<dim3(6, 32), 128>>>(pSh, pSl, pR1h, pR1l, pR2); // R2 = S @ R1

    // node projections
    k_proj<<<dim3(125, 13), 256>>>(ne, wp, WCOLS, 0);
    k_proj<<<dim3(125, 1), 256>>>(ne, bp, Oo, 1);
    k_proj<<<dim3(125, 1), 256>>>(ne, wwt_p, 128, 2);
    k_proj<<<dim3(125, 1), 256>>>(ne, wws_p, 32, 3);

    // ZFC rowsums
    k_rs<<<Nn, 256>>>(gnn_w);

    // supra branch
    k_uv<<<(Bb * Ee + 255) / 256, 256>>>(xew, bidx, lw, lb);
    k_hodge<<<dim3((Ee + 255) / 256, HCH), 256>>>(hodge);
    k_ybar<<<(Bb * Ee + 255) / 256, 256>>>(p_jmp);
    k_m<<<dim3((Nn + 31) / 32, MKS), 256>>>(inc);

    // temporal branch
    k_xw<<<(Bb * Nn + 255) / 256, 256>>>(xwin, Tp);

    // fused output
    k_assembly<<<Nn, 256>>>(x, zfc, gnn_b, out);
}

// round 3
// speedup vs baseline: 1.5435x; 1.0039x over previous
#include <cuda_runtime.h>
#include <cuda_bf16.h>
#include <math.h>

typedef unsigned short ushortT;
typedef unsigned int uintT;

// ---------------- problem dims ----------------
constexpr int Bb = 16, Nn = 2000, Ee = 3000, Cc = 17, Ww = 12, Dd = 16, Oo = 256, Kk = 3, NBt = 3;
constexpr int BCP   = 288;           // padded packed columns (272 valid)
constexpr int KC    = Kk * Cc;       // 51
constexpr int WCOLS = KC * 64;       // 3264
constexpr int HCH   = 16;            // hodge K-split chunks
constexpr int MKS   = 4;             // inc GEMM K-splits

// ---------------- scratch (device globals, no allocation) ----------------
__device__ __align__(16) float  g_S[Nn * Nn];
__device__ __align__(16) float  g_cinv[Nn];
__device__ __align__(16) ushortT g_Sh[Nn * Nn];
__device__ __align__(16) ushortT g_Sl[Nn * Nn];
__device__ __align__(16) ushortT g_Xh[Nn * BCP];
__device__ __align__(16) ushortT g_Xl[Nn * BCP];
__device__ __align__(16) ushortT g_R1h[Nn * BCP];
__device__ __align__(16) ushortT g_R1l[Nn * BCP];
__device__ __align__(16) float  g_R1[Nn * BCP];
__device__ __align__(16) float  g_R2[Nn * BCP];
__device__ float g_W   [Nn * WCOLS];
__device__ float g_bias[Nn * Oo];
__device__ float g_wwt [Nn * 128];
__device__ float g_wws [Nn * 32];
__device__ float g_U[Bb * Ee];
__device__ float g_V[Bb * Ee];
__device__ float g_Hpart[HCH * Bb * Ee];
__device__ float g_Ybar[Bb * Ee];
__device__ float g_Mpart[MKS * Bb * Nn];
__device__ float g_XW[Bb * Nn];
__device__ float g_rs[Nn];

__device__ __forceinline__ float scalar_val(const void* p) {
    int v = *(const int*)p;
    if (v > -100000000 && v < 100000000) return (float)v;
    return __int_as_float(v);
}
__device__ __forceinline__ ushortT f2bf(float v) {
    __nv_bfloat16 b = __float2bfloat16(v);
    return *reinterpret_cast<ushortT*>(&b);
}
__device__ __forceinline__ float bf2f(ushortT u) {
    __nv_bfloat16 b; *reinterpret_cast<ushortT*>(&b) = u;
    return __bfloat162float(b);
}

// block reduce (256 threads) helpers
__device__ __forceinline__ float blk_max(float v, float* red) {
    #pragma unroll
    for (int o = 16; o > 0; o >>= 1) v = fmaxf(v, __shfl_xor_sync(0xffffffffu, v, o));
    int t = threadIdx.x;
    if ((t & 31) == 0) red[t >> 5] = v;
    __syncthreads();
    if (t < 8) {
        v = red[t];
        #pragma unroll
        for (int o = 4; o > 0; o >>= 1) v = fmaxf(v, __shfl_xor_sync(0xffu, v, o));
        if (t == 0) red[0] = v;
    }
    __syncthreads();
    v = red[0];
    __syncthreads();
    return v;
}
__device__ __forceinline__ float blk_sum(float v, float* red) {
    #pragma unroll
    for (int o = 16; o > 0; o >>= 1) v += __shfl_xor_sync(0xffffffffu, v, o);
    int t = threadIdx.x;
    if ((t & 31) == 0) red[t >> 5] = v;
    __syncthreads();
    if (t < 8) {
        v = red[t];
        #pragma unroll
        for (int o = 4; o > 0; o >>= 1) v += __shfl_xor_sync(0xffu, v, o);
        if (t == 0) red[0] = v;
    }
    __syncthreads();
    v = red[0];
    __syncthreads();
    return v;
}

// ---------------- S0 = relu(ne @ ne^T), diag = stay ----------------
__global__ void k_s0(const float* __restrict__ ne, const void* p_stay) {
    __shared__ float a_s[16][17], b_s[16][17];
    int i0 = blockIdx.y * 16, j0 = blockIdx.x * 16;
    int t = threadIdx.x;
    int r = t >> 4, d = t & 15;
    a_s[r][d] = (i0 + r < Nn) ? ne[(i0 + r) * Dd + d] : 0.f;
    b_s[r][d] = (j0 + r < Nn) ? ne[(j0 + r) * Dd + d] : 0.f;
    __syncthreads();
    int ty = t >> 4, tx = t & 15;
    int i = i0 + ty, j = j0 + tx;
    if (i < Nn && j < Nn) {
        float acc = 0.f;
        #pragma unroll
        for (int dd = 0; dd < 16; dd++) acc += a_s[ty][dd] * b_s[tx][dd];
        acc = fmaxf(acc, 0.f);
        if (i == j) acc = scalar_val(p_stay);
        g_S[(size_t)i * Nn + j] = acc;
    }
}

// ---------------- fused softmax + bf16 hi/lo split + colscale recip ----------------
// Writes row-normalized Snorm (softmax path) or raw adj*exp (fixed path) as bf16
// hi/lo; g_cinv[i] = 1 / (sum of the written row values).
__global__ void k_softmax_split(const void* p_fixed, const float* __restrict__ adj) {
    __shared__ float row[Nn];
    __shared__ float red[8];
    int i = blockIdx.x, t = threadIdx.x;
    bool fixed = (scalar_val(p_fixed) != 0.f);
    for (int j = t; j < Nn; j += 256) row[j] = g_S[(size_t)i * Nn + j];
    __syncthreads();
    float outsum;
    if (!fixed) {
        float m = -1e30f;
        for (int j = t; j < Nn; j += 256) m = fmaxf(m, row[j]);
        m = blk_max(m, red);
        float s = 0.f;
        for (int j = t; j < Nn; j += 256) { float e = __expf(row[j] - m); row[j] = e; s += e; }
        s = blk_sum(s, red);
        float inv = 1.f / s;
        float fs = 0.f;
        for (int j = t; j < Nn; j += 256) {
            float v = row[j] * inv;
            ushortT h = f2bf(v);
            g_Sh[(size_t)i * Nn + j] = h;
            g_Sl[(size_t)i * Nn + j] = f2bf(v - bf2f(h));
            fs += v;
        }
        outsum = blk_sum(fs, red);
    } else {
        float fs = 0.f;
        for (int j = t; j < Nn; j += 256) {
            float v = adj[(size_t)i * Nn + j] * __expf(row[j]);
            ushortT h = f2bf(v);
            g_Sh[(size_t)i * Nn + j] = h;
            g_Sl[(size_t)i * Nn + j] = f2bf(v - bf2f(h));
            fs += v;
        }
        outsum = blk_sum(fs, red);
    }
    if (t == 0) g_cinv[i] = 1.f / outsum;
}

// ---------------- x (B,N,C) -> bf16 hi/lo packed [m][288], row-scaled by cinv ----------------
__global__ void k_splitX(const float* __restrict__ x) {
    int idx = blockIdx.x * 256 + threadIdx.x;
    if (idx >= Nn * BCP) return;
    int m = idx / BCP, q = idx % BCP;
    float v = 0.f;
    if (q < Bb * Cc) {
        int b = q / Cc, c = q % Cc;
        v = x[((size_t)b * Nn + m) * Cc + c] * g_cinv[m];
    }
    ushortT h = f2bf(v);
    g_Xh[idx] = h;
    g_Xl[idx] = f2bf(v - bf2f(h));
}

// ---------------- R1 fp32 -> bf16 hi/lo, row-scaled by cinv ----------------
__global__ void k_splitR1() {
    int i4 = blockIdx.x * 256 + threadIdx.x;
    if (i4 >= Nn * BCP / 4) return;
    int m = (i4 * 4) / BCP;
    float ci = g_cinv[m];
    float4 s = ((const float4*)g_R1)[i4];
    float v[4] = { s.x * ci, s.y * ci, s.z * ci, s.w * ci };
    ushort4 hh, ll;
    ushortT* hp = &hh.x; ushortT* lp = &ll.x;
    #pragma unroll
    for (int q = 0; q < 4; q++) {
        ushortT h = f2bf(v[q]);
        hp[q] = h;
        lp[q] = f2bf(v[q] - bf2f(h));
    }
    ((ushort4*)g_R1h)[i4] = hh;
    ((ushort4*)g_R1l)[i4] = ll;
}

// ---------------- tensor-core GEMM: C[2000,288] = A[2000,2000] @ B[2000,288] ----------------
// bf16x3 compensated: C = Ah*Bh + Ah*Bl + Al*Bh, fp32 accum.
__device__ __forceinline__ void ldsm_x4(uintT* r, uintT addr) {
    asm volatile("ldmatrix.sync.aligned.m8n8.x4.shared.b16 {%0,%1,%2,%3}, [%4];"
                 : "=r"(r[0]), "=r"(r[1]), "=r"(r[2]), "=r"(r[3]) : "r"(addr));
}
__device__ __forceinline__ void ldsm_x2t(uintT* r, uintT addr) {
    asm volatile("ldmatrix.sync.aligned.m8n8.x2.trans.shared.b16 {%0,%1}, [%2];"
                 : "=r"(r[0]), "=r"(r[1]) : "r"(addr));
}
__device__ __forceinline__ void mma16816(float* c, const uintT* a, const uintT* b) {
    asm volatile("mma.sync.aligned.m16n8k16.row.col.f32.bf16.bf16.f32 "
                 "{%0,%1,%2,%3}, {%4,%5,%6,%7}, {%8,%9}, {%0,%1,%2,%3};"
                 : "+f"(c[0]), "+f"(c[1]), "+f"(c[2]), "+f"(c[3])
                 : "r"(a[0]), "r"(a[1]), "r"(a[2]), "r"(a[3]), "r"(b[0]), "r"(b[1]));
}

__global__ void __launch_bounds__(128) k_mmagemm(
        const ushortT* __restrict__ Ah, const ushortT* __restrict__ Al,
        const ushortT* __restrict__ Bh, const ushortT* __restrict__ Bl,
        float* __restrict__ Cm) {
    constexpr int ASTR = 24;  // bf16 units per A smem row (16 + 8 pad)
    constexpr int BSTR = 56;  // bf16 units per B smem row (48 + 8 pad)
    __shared__ ushortT sAh[2][64 * ASTR], sAl[2][64 * ASTR];
    __shared__ ushortT sBh[2][16 * BSTR], sBl[2][16 * BSTR];

    int t = threadIdx.x;
    int warp = t >> 5, lane = t & 31;
    int wm = (warp >> 1) * 32, wn = (warp & 1) * 24;
    int bm0 = blockIdx.y * 64, bn0 = blockIdx.x * 48;

    int ar = t >> 1, ak = (t & 1) * 8;   // A: row 0..63, k-half 0/8
    int br = t / 6,  bs = t % 6;         // B: k-row 0..15, 8-col seg (valid t<96)
    bool bact = t < 96;

    float acc[2][3][4];
    #pragma unroll
    for (int i = 0; i < 2; i++)
        #pragma unroll
        for (int j = 0; j < 3; j++)
            #pragma unroll
            for (int q = 0; q < 4; q++) acc[i][j][q] = 0.f;

    uint4 pAh, pAl, pBh, pBl;
    pBh = make_uint4(0,0,0,0); pBl = pBh;

    // prologue load kb=0
    {
        int gr = bm0 + ar;
        if (gr < Nn) {
            size_t off = (size_t)gr * Nn + ak;
            pAh = *(const uint4*)(Ah + off);
            pAl = *(const uint4*)(Al + off);
        } else { pAh = make_uint4(0,0,0,0); pAl = pAh; }
        if (bact) {
            size_t off = (size_t)br * BCP + bn0 + bs * 8;
            pBh = *(const uint4*)(Bh + off);
            pBl = *(const uint4*)(Bl + off);
        }
        *(uint4*)&sAh[0][ar * ASTR + ak] = pAh;
        *(uint4*)&sAl[0][ar * ASTR + ak] = pAl;
        if (bact) {
            *(uint4*)&sBh[0][br * BSTR + bs * 8] = pBh;
            *(uint4*)&sBl[0][br * BSTR + bs * 8] = pBl;
        }
    }
    __syncthreads();

    uintT aoff = ((wm + (lane & 15)) * ASTR + ((lane & 16) ? 8 : 0)) * 2;
    uintT boff = ((lane & 15) * BSTR + wn) * 2;
    uintT baseAh0 = (uintT)__cvta_generic_to_shared(&sAh[0][0]);
    uintT baseAl0 = (uintT)__cvta_generic_to_shared(&sAl[0][0]);
    uintT baseBh0 = (uintT)__cvta_generic_to_shared(&sBh[0][0]);
    uintT baseBl0 = (uintT)__cvta_generic_to_shared(&sBl[0][0]);
    constexpr uintT abufB = 64 * ASTR * 2;
    constexpr uintT bbufB = 16 * BSTR * 2;

    constexpr int NKB = Nn / 16;  // 125
    for (int kb = 0; kb < NKB; kb++) {
        int cur = kb & 1;
        if (kb < NKB - 1) {  // prefetch next tile into regs
            int gr = bm0 + ar;
            if (gr < Nn) {
                size_t off = (size_t)gr * Nn + (kb + 1) * 16 + ak;
                pAh = *(const uint4*)(Ah + off);
                pAl = *(const uint4*)(Al + off);
            } else { pAh = make_uint4(0,0,0,0); pAl = pAh; }
            if (bact) {
                size_t off = (size_t)((kb + 1) * 16 + br) * BCP + bn0 + bs * 8;
                pBh = *(const uint4*)(Bh + off);
                pBl = *(const uint4*)(Bl + off);
            }
        }
        uintT fah[2][4], fal[2][4], fbh[3][2], fbl[3][2];
        #pragma unroll
        for (int mt = 0; mt < 2; mt++) {
            ldsm_x4(fah[mt], baseAh0 + cur * abufB + aoff + mt * 16 * ASTR * 2);
            ldsm_x4(fal[mt], baseAl0 + cur * abufB + aoff + mt * 16 * ASTR * 2);
        }
        #pragma unroll
        for (int nt = 0; nt < 3; nt++) {
            ldsm_x2t(fbh[nt], baseBh0 + cur * bbufB + boff + nt * 16);
            ldsm_x2t(fbl[nt], baseBl0 + cur * bbufB + boff + nt * 16);
        }
        #pragma unroll
        for (int mt = 0; mt < 2; mt++)
            #pragma unroll
            for (int nt = 0; nt < 3; nt++) {
                mma16816(acc[mt][nt], fah[mt], fbh[nt]);
                mma16816(acc[mt][nt], fah[mt], fbl[nt]);
                mma16816(acc[mt][nt], fal[mt], fbh[nt]);
            }
        __syncthreads();
        if (kb < NKB - 1) {
            int nxt = cur ^ 1;
            *(uint4*)&sAh[nxt][ar * ASTR + ak] = pAh;
            *(uint4*)&sAl[nxt][ar * ASTR + ak] = pAl;
            if (bact) {
                *(uint4*)&sBh[nxt][br * BSTR + bs * 8] = pBh;
                *(uint4*)&sBl[nxt][br * BSTR + bs * 8] = pBl;
            }
            __syncthreads();
        }
    }
    // epilogue
    #pragma unroll
    for (int mt = 0; mt < 2; mt++)
        #pragma unroll
        for (int nt = 0; nt < 3; nt++) {
            int row = bm0 + wm + mt * 16 + (lane >> 2);
            int col = bn0 + wn + nt * 8 + (lane & 3) * 2;
            if (row < Nn)
                *(float2*)&Cm[(size_t)row * BCP + col] = make_float2(acc[mt][nt][0], acc[mt][nt][1]);
            if (row + 8 < Nn)
                *(float2*)&Cm[(size_t)(row + 8) * BCP + col] = make_float2(acc[mt][nt][2], acc[mt][nt][3]);
        }
}

// ---------------- node projections ----------------
__global__ void k_proj(const float* __restrict__ ne, const float* __restrict__ pool,
                       int cols, int mode) {
    __shared__ float p_s[16][256];
    __shared__ float ne_s[16][17];
    int n0 = blockIdx.x * 16;
    int c0 = blockIdx.y * 256;
    int t = threadIdx.x;
    for (int d = 0; d < 16; d++)
        p_s[d][t] = (c0 + t < cols) ? pool[(size_t)d * cols + c0 + t] : 0.f;
    { int nn = t >> 4, d = t & 15; ne_s[nn][d] = (n0 + nn < Nn) ? ne[(n0 + nn) * 16 + d] : 0.f; }
    __syncthreads();
    int c = c0 + t;
    if (c >= cols) return;
    float* outp = (mode == 0) ? g_W : (mode == 1) ? g_bias : (mode == 2) ? g_wwt : g_wws;
    for (int nn = 0; nn < 16; nn++) {
        if (n0 + nn >= Nn) break;
        float acc = 0.f;
        #pragma unroll
        for (int d = 0; d < 16; d++) acc += ne_s[nn][d] * p_s[d][t];
        outp[(size_t)(n0 + nn) * cols + c] = acc;
    }
}

// ---------------- gnn_w row sums ----------------
__global__ void k_rs(const float* __restrict__ gnn_w) {
    __shared__ float red[8];
    int m = blockIdx.x, t = threadIdx.x;
    float s = 0.f;
    for (int j = t; j < Nn; j += 256) s += gnn_w[(size_t)m * Nn + j];
    s = blk_sum(s, red);
    if (t == 0) g_rs[m] = s;
}

// ---------------- U,V from bootstrap-gathered xe ----------------
__global__ void k_uv(const float* __restrict__ xew, const int* __restrict__ bidx,
                     const float* __restrict__ lw, const float* __restrict__ lb) {
    int idx = blockIdx.x * 256 + threadIdx.x;
    if (idx >= Bb * Ee) return;
    int b = idx / Ee, i = idx % Ee;
    float w = lw[0], bia = lb[0];
    float u = 0.f, v = 0.f;
    #pragma unroll
    for (int f = 0; f < NBt; f++) {
        int tt = bidx[f]; tt = max(0, min(Ww - 1, tt));
        float xv = xew[((size_t)(b * Ww + tt)) * Ee + i] * w + bia;
        u += xv; v += (float)(NBt - 1 - f) * xv;
    }
    g_U[idx] = u; g_V[idx] = v;
}

// ---------------- hodge partials ----------------
__global__ void k_hodge(const float* __restrict__ hodge) {
    __shared__ float u_s[16][192];
    constexpr int CL = (Ee + HCH - 1) / HCH; // 188
    int ch = blockIdx.y;
    int i0 = ch * CL;
    int ilen = min(CL, Ee - i0);
    int t = threadIdx.x;
    for (int idx = t; idx < Bb * ilen; idx += 256) {
        int bb = idx / ilen, ii = idx % ilen;
        u_s[bb][ii] = g_U[bb * Ee + i0 + ii];
    }
    __syncthreads();
    int j = blockIdx.x * 256 + t;
    if (j >= Ee) return;
    float acc[16];
    #pragma unroll
    for (int bb = 0; bb < 16; bb++) acc[bb] = 0.f;
    for (int ii = 0; ii < ilen; ii++) {
        float h = hodge[(size_t)(i0 + ii) * Ee + j];
        #pragma unroll
        for (int bb = 0; bb < 16; bb++) acc[bb] += u_s[bb][ii] * h;
    }
    #pragma unroll
    for (int bb = 0; bb < 16; bb++)
        g_Hpart[((size_t)ch * Bb + bb) * Ee + j] = acc[bb];
}

__global__ void k_ybar(const void* p_jump) {
    int idx = blockIdx.x * 256 + threadIdx.x;
    if (idx >= Bb * Ee) return;
    int b = idx / Ee, j = idx % Ee;
    float jump = scalar_val(p_jump);
    float s = jump * g_V[idx];
    #pragma unroll
    for (int ch = 0; ch < HCH; ch++) s += g_Hpart[((size_t)ch * Bb + b) * Ee + j];
    g_Ybar[idx] = s * (1.f / (float)NBt);
}

// ---------------- Mpart[sp,b,n] = sum_{e in split} Ybar[b,e]*inc[n,e] ----------------
__global__ void k_m(const float* __restrict__ inc) {
    __shared__ float inc_s[32][65];
    __shared__ float yb_s[16][64];
    constexpr int SL = Ee / MKS; // 750
    int n0 = blockIdx.x * 32;
    int sp = blockIdx.y;
    int e_start = sp * SL, e_end = e_start + SL;
    int t = threadIdx.x;
    int nl = t & 31, bg = t >> 5;
    int b0 = bg * 2, b1 = bg * 2 + 1;
    float acc0 = 0.f, acc1 = 0.f;
    for (int e0 = e_start; e0 < e_end; e0 += 64) {
        for (int idx = t; idx < 32 * 64; idx += 256) {
            int r = idx >> 6, c = idx & 63;
            int n = n0 + r, e = e0 + c;
            inc_s[r][c] = (n < Nn && e < e_end) ? inc[(size_t)n * Ee + e] : 0.f;
        }
        for (int idx = t; idx < 16 * 64; idx += 256) {
            int bb = idx >> 6, c = idx & 63;
            int e = e0 + c;
            yb_s[bb][c] = (e < e_end) ? g_Ybar[bb * Ee + e] : 0.f;
        }
        __syncthreads();
        #pragma unroll
        for (int c = 0; c < 64; c++) {
            float w = inc_s[nl][c];
            acc0 += yb_s[b0][c] * w;
            acc1 += yb_s[b1][c] * w;
        }
        __syncthreads();
    }
    int n = n0 + nl;
    if (n < Nn) {
        g_Mpart[((size_t)sp * Bb + b0) * Nn + n] = acc0;
        g_Mpart[((size_t)sp * Bb + b1) * Nn + n] = acc1;
    }
}

// ---------------- XW[b,n] = sum_t x_window[b,t,n]*Tp[t] ----------------
__global__ void k_xw(const float* __restrict__ xwin, const float* __restrict__ Tp) {
    int idx = blockIdx.x * 256 + threadIdx.x;
    if (idx >= Bb * Nn) return;
    int b = idx / Nn, n = idx % Nn;
    float s = 0.f;
    #pragma unroll
    for (int t = 0; t < Ww; t++) s += xwin[((size_t)(b * Ww + t)) * Nn + n] * Tp[t];
    g_XW[idx] = s;
}

// ---------------- fused assembly ----------------
__global__ void k_assembly(const float* __restrict__ x, const float* __restrict__ zfc_in,
                           const float* __restrict__ gnn_b, float* __restrict__ out) {
    __shared__ float xs_s[16][52];
    __shared__ float zfc_s[16][32];
    __shared__ float xw_s[16];
    __shared__ float m_s[16];
    int n = blockIdx.x;
    int t = threadIdx.x;
    for (int idx = t; idx < Bb * KC; idx += 256) {   // 816 values
        int b = idx / KC, ki = idx % KC;
        int k = ki / Cc, c = ki % Cc;
        float v;
        if (k == 0)      v = x[((size_t)b * Nn + n) * Cc + c];
        else if (k == 1) v = g_R1[(size_t)n * BCP + b * Cc + c];
        else             v = g_R2[(size_t)n * BCP + b * Cc + c];
        xs_s[b][ki] = v;
    }
    for (int idx = t; idx < Bb * 32; idx += 256)
        zfc_s[idx >> 5][idx & 31] = zfc_in[idx];
    if (t < 16) {
        xw_s[t] = g_XW[t * Nn + n];
        float ms = 0.f;
        #pragma unroll
        for (int sp = 0; sp < MKS; sp++) ms += g_Mpart[((size_t)sp * Bb + t) * Nn + n];
        m_s[t] = ms;
    }
    __syncthreads();

    int o = t;
    float biasv = g_bias[(size_t)n * Oo + o];
    if (o < 64) {                       // graph diffusion branch
        float w[KC];
        #pragma unroll
        for (int ki = 0; ki < KC; ki++) w[ki] = g_W[(size_t)n * WCOLS + ki * 64 + o];
        for (int b = 0; b < 16; b++) {
            float acc = 0.f;
            #pragma unroll
            for (int ki = 0; ki < KC; ki++) acc += xs_s[b][ki] * w[ki];
            out[((size_t)b * Nn + n) * Oo + o] = acc + biasv;
        }
    } else if (o < 96) {                // ZFC branch (reshape-aware)
        int c = o - 64;
        int flat = n * 32 + c;
        int r = flat / Nn;
        int m = flat - r * Nn;
        float rsv = g_rs[m], gb = gnn_b[m];
        for (int b = 0; b < 16; b++) {
            float v = fmaxf(zfc_s[b][r] * rsv + gb, 0.f);
            out[((size_t)b * Nn + n) * Oo + o] = v + biasv;
        }
    } else if (o < 224) {               // temporal branch
        float wv = g_wwt[(size_t)n * 128 + (o - 96)];
        for (int b = 0; b < 16; b++)
            out[((size_t)b * Nn + n) * Oo + o] = xw_s[b] * wv + biasv;
    } else {                            // supra / hypergraph branch
        float wv = g_wws[(size_t)n * 32 + (o - 224)];
        for (int b = 0; b < 16; b++)
            out[((size_t)b * Nn + n) * Oo + o] = m_s[b] * wv + biasv;
    }
}

// ---------------- host launch ----------------
extern "C" void kernel_launch(void* const* d_in, const int* in_sizes, int n_in,
                              void* d_out, int out_size) {
    const float* x     = (const float*)d_in[0];
    const float* xwin  = (const float*)d_in[1];
    const float* ne    = (const float*)d_in[2];
    const void*  p_fix = d_in[3];
    const float* adj   = (const float*)d_in[4];
    const void*  p_sty = d_in[5];
    const void*  p_jmp = d_in[6];
    const float* zfc   = (const float*)d_in[7];
    const float* hodge = (const float*)d_in[8];
    const float* xew   = (const float*)d_in[9];
    const float* inc   = (const float*)d_in[10];
    const float* wp    = (const float*)d_in[11];
    const float* wws_p = (const float*)d_in[12];
    const float* wwt_p = (const float*)d_in[13];
    const float* bp    = (const float*)d_in[14];
    const float* Tp    = (const float*)d_in[15];
    const float* lw    = (const float*)d_in[16];
    const float* lb    = (const float*)d_in[17];
    const float* gnn_w = (const float*)d_in[18];
    const float* gnn_b = (const float*)d_in[19];
    const int*   bidx  = (const int*)d_in[20];
    float* out = (float*)d_out;

    static ushortT *pSh = nullptr, *pSl, *pXh, *pXl, *pR1h, *pR1l;
    static float *pR1, *pR2;
    if (!pSh) {
        cudaGetSymbolAddress((void**)&pSh,  g_Sh);
        cudaGetSymbolAddress((void**)&pSl,  g_Sl);
        cudaGetSymbolAddress((void**)&pXh,  g_Xh);
        cudaGetSymbolAddress((void**)&pXl,  g_Xl);
        cudaGetSymbolAddress((void**)&pR1h, g_R1h);
        cudaGetSymbolAddress((void**)&pR1l, g_R1l);
        cudaGetSymbolAddress((void**)&pR1,  g_R1);
        cudaGetSymbolAddress((void**)&pR2,  g_R2);
    }

    // S pipeline (critical path); GEMM1 placed 4th so the -s 5 profile lands on it
    k_s0<<<dim3(125, 125), 256>>>(ne, p_sty);                    // 1
    k_softmax_split<<<Nn, 256>>>(p_fix, adj);                    // 2
    k_splitX<<<(Nn * BCP + 255) / 256, 256>>>(x);                // 3
    k_mmagemm<<<dim3(6, 32), 128>>>(pSh, pSl, pXh, pXl, pR1);    // 4: R1 = S' @ X
    k_splitR1<<<(Nn * BCP / 4 + 255) / 256, 256>>>();            // 5
    k_mmagemm<<<dim3(6, 32), 128>>>(pSh, pSl, pR1h, pR1l, pR2);  // 6: R2 = S' @ R1

    // independent branches
    k_proj<<<dim3(125, 13), 256>>>(ne, wp, WCOLS, 0);
    k_proj<<<dim3(125, 1), 256>>>(ne, bp, Oo, 1);
    k_proj<<<dim3(125, 1), 256>>>(ne, wwt_p, 128, 2);
    k_proj<<<dim3(125, 1), 256>>>(ne, wws_p, 32, 3);
    k_rs<<<Nn, 256>>>(gnn_w);
    k_uv<<<(Bb * Ee + 255) / 256, 256>>>(xew, bidx, lw, lb);
    k_hodge<<<dim3((Ee + 255) / 256, HCH), 256>>>(hodge);
    k_ybar<<<(Bb * Ee + 255) / 256, 256>>>(p_jmp);
    k_m<<<dim3((Nn + 31) / 32, MKS), 256>>>(inc);
    k_xw<<<(Bb * Nn + 255) / 256, 256>>>(xwin, Tp);

    // fused output
    k_assembly<<<Nn, 256>>>(x, zfc, gnn_b, out);
}

// round 4
// speedup vs baseline: 1.6676x; 1.0804x over previous
#include <cuda_runtime.h>
#include <cuda_bf16.h>
#include <math.h>

typedef unsigned short ushortT;
typedef unsigned int uintT;

// ---------------- problem dims ----------------
constexpr int Bb = 16, Nn = 2000, Ee = 3000, Cc = 17, Ww = 12, Dd = 16, Oo = 256, Kk = 3, NBt = 3;
constexpr int BCP   = 288;           // padded packed columns (272 valid)
constexpr int KC    = Kk * Cc;       // 51
constexpr int WCOLS = KC * 64;       // 3264
constexpr int HCH   = 16;            // hodge K-split chunks
constexpr int MKS   = 4;             // inc GEMM K-splits
constexpr int KSP   = 5;             // GEMM split-K factor (125 k-blocks / 5 = 25)
constexpr int NKBS  = 25;            // k-blocks per split

// ---------------- scratch (device globals, no allocation) ----------------
__device__ __align__(16) float  g_S[Nn * Nn];
__device__ __align__(16) float  g_cinv[Nn];
__device__ __align__(16) ushortT g_Sh[Nn * Nn];
__device__ __align__(16) ushortT g_Sl[Nn * Nn];
__device__ __align__(16) ushortT g_Xh[Nn * BCP];
__device__ __align__(16) ushortT g_Xl[Nn * BCP];
__device__ __align__(16) ushortT g_R1h[Nn * BCP];
__device__ __align__(16) ushortT g_R1l[Nn * BCP];
__device__ __align__(16) float  g_R1[Nn * BCP];
__device__ __align__(16) float  g_R2[Nn * BCP];
__device__ __align__(16) float  g_Cpart[KSP * Nn * BCP];
__device__ float g_W   [Nn * WCOLS];
__device__ float g_bias[Nn * Oo];
__device__ float g_wwt [Nn * 128];
__device__ float g_wws [Nn * 32];
__device__ float g_U[Bb * Ee];
__device__ float g_V[Bb * Ee];
__device__ float g_Hpart[HCH * Bb * Ee];
__device__ float g_Ybar[Bb * Ee];
__device__ float g_Mpart[MKS * Bb * Nn];
__device__ float g_XW[Bb * Nn];
__device__ float g_rs[Nn];

__device__ __forceinline__ float scalar_val(const void* p) {
    int v = *(const int*)p;
    if (v > -100000000 && v < 100000000) return (float)v;
    return __int_as_float(v);
}
__device__ __forceinline__ ushortT f2bf(float v) {
    __nv_bfloat16 b = __float2bfloat16(v);
    return *reinterpret_cast<ushortT*>(&b);
}
__device__ __forceinline__ float bf2f(ushortT u) {
    __nv_bfloat16 b; *reinterpret_cast<ushortT*>(&b) = u;
    return __bfloat162float(b);
}

__device__ __forceinline__ float blk_max(float v, float* red) {
    #pragma unroll
    for (int o = 16; o > 0; o >>= 1) v = fmaxf(v, __shfl_xor_sync(0xffffffffu, v, o));
    int t = threadIdx.x;
    if ((t & 31) == 0) red[t >> 5] = v;
    __syncthreads();
    if (t < 8) {
        v = red[t];
        #pragma unroll
        for (int o = 4; o > 0; o >>= 1) v = fmaxf(v, __shfl_xor_sync(0xffu, v, o));
        if (t == 0) red[0] = v;
    }
    __syncthreads();
    v = red[0];
    __syncthreads();
    return v;
}
__device__ __forceinline__ float blk_sum(float v, float* red) {
    #pragma unroll
    for (int o = 16; o > 0; o >>= 1) v += __shfl_xor_sync(0xffffffffu, v, o);
    int t = threadIdx.x;
    if ((t & 31) == 0) red[t >> 5] = v;
    __syncthreads();
    if (t < 8) {
        v = red[t];
        #pragma unroll
        for (int o = 4; o > 0; o >>= 1) v += __shfl_xor_sync(0xffu, v, o);
        if (t == 0) red[0] = v;
    }
    __syncthreads();
    v = red[0];
    __syncthreads();
    return v;
}

// ---------------- S0 = relu(ne @ ne^T), diag = stay ----------------
__global__ void k_s0(const float* __restrict__ ne, const void* p_stay) {
    __shared__ float a_s[16][17], b_s[16][17];
    int i0 = blockIdx.y * 16, j0 = blockIdx.x * 16;
    int t = threadIdx.x;
    int r = t >> 4, d = t & 15;
    a_s[r][d] = (i0 + r < Nn) ? ne[(i0 + r) * Dd + d] : 0.f;
    b_s[r][d] = (j0 + r < Nn) ? ne[(j0 + r) * Dd + d] : 0.f;
    __syncthreads();
    int ty = t >> 4, tx = t & 15;
    int i = i0 + ty, j = j0 + tx;
    if (i < Nn && j < Nn) {
        float acc = 0.f;
        #pragma unroll
        for (int dd = 0; dd < 16; dd++) acc += a_s[ty][dd] * b_s[tx][dd];
        acc = fmaxf(acc, 0.f);
        if (i == j) acc = scalar_val(p_stay);
        g_S[(size_t)i * Nn + j] = acc;
    }
}

// ---------------- fused softmax + bf16 hi/lo split + colscale recip ----------------
__global__ void k_softmax_split(const void* p_fixed, const float* __restrict__ adj) {
    __shared__ float row[Nn];
    __shared__ float red[8];
    int i = blockIdx.x, t = threadIdx.x;
    bool fixed = (scalar_val(p_fixed) != 0.f);
    for (int j = t; j < Nn; j += 256) row[j] = g_S[(size_t)i * Nn + j];
    __syncthreads();
    float outsum;
    if (!fixed) {
        float m = -1e30f;
        for (int j = t; j < Nn; j += 256) m = fmaxf(m, row[j]);
        m = blk_max(m, red);
        float s = 0.f;
        for (int j = t; j < Nn; j += 256) { float e = __expf(row[j] - m); row[j] = e; s += e; }
        s = blk_sum(s, red);
        float inv = 1.f / s;
        float fs = 0.f;
        for (int j = t; j < Nn; j += 256) {
            float v = row[j] * inv;
            ushortT h = f2bf(v);
            g_Sh[(size_t)i * Nn + j] = h;
            g_Sl[(size_t)i * Nn + j] = f2bf(v - bf2f(h));
            fs += v;
        }
        outsum = blk_sum(fs, red);
    } else {
        float fs = 0.f;
        for (int j = t; j < Nn; j += 256) {
            float v = adj[(size_t)i * Nn + j] * __expf(row[j]);
            ushortT h = f2bf(v);
            g_Sh[(size_t)i * Nn + j] = h;
            g_Sl[(size_t)i * Nn + j] = f2bf(v - bf2f(h));
            fs += v;
        }
        outsum = blk_sum(fs, red);
    }
    if (t == 0) g_cinv[i] = 1.f / outsum;
}

// ---------------- x (B,N,C) -> bf16 hi/lo packed [m][288], row-scaled by cinv ----------------
__global__ void k_splitX(const float* __restrict__ x) {
    int idx = blockIdx.x * 256 + threadIdx.x;
    if (idx >= Nn * BCP) return;
    int m = idx / BCP, q = idx % BCP;
    float v = 0.f;
    if (q < Bb * Cc) {
        int b = q / Cc, c = q % Cc;
        v = x[((size_t)b * Nn + m) * Cc + c] * g_cinv[m];
    }
    ushortT h = f2bf(v);
    g_Xh[idx] = h;
    g_Xl[idx] = f2bf(v - bf2f(h));
}

// ---------------- split-K tensor-core GEMM partials ----------------
// Cpart[z][m][n] = sum over k-blocks [z*25,(z+1)*25) of A@B (bf16x3 compensated).
__device__ __forceinline__ void ldsm_x4(uintT* r, uintT addr) {
    asm volatile("ldmatrix.sync.aligned.m8n8.x4.shared.b16 {%0,%1,%2,%3}, [%4];"
                 : "=r"(r[0]), "=r"(r[1]), "=r"(r[2]), "=r"(r[3]) : "r"(addr));
}
__device__ __forceinline__ void ldsm_x2t(uintT* r, uintT addr) {
    asm volatile("ldmatrix.sync.aligned.m8n8.x2.trans.shared.b16 {%0,%1}, [%2];"
                 : "=r"(r[0]), "=r"(r[1]) : "r"(addr));
}
__device__ __forceinline__ void mma16816(float* c, const uintT* a, const uintT* b) {
    asm volatile("mma.sync.aligned.m16n8k16.row.col.f32.bf16.bf16.f32 "
                 "{%0,%1,%2,%3}, {%4,%5,%6,%7}, {%8,%9}, {%0,%1,%2,%3};"
                 : "+f"(c[0]), "+f"(c[1]), "+f"(c[2]), "+f"(c[3])
                 : "r"(a[0]), "r"(a[1]), "r"(a[2]), "r"(a[3]), "r"(b[0]), "r"(b[1]));
}

__global__ void __launch_bounds__(128) k_mmagemm(
        const ushortT* __restrict__ Ah, const ushortT* __restrict__ Al,
        const ushortT* __restrict__ Bh, const ushortT* __restrict__ Bl) {
    constexpr int ASTR = 24;
    constexpr int BSTR = 56;
    __shared__ ushortT sAh[2][64 * ASTR], sAl[2][64 * ASTR];
    __shared__ ushortT sBh[2][16 * BSTR], sBl[2][16 * BSTR];

    int t = threadIdx.x;
    int warp = t >> 5, lane = t & 31;
    int wm = (warp >> 1) * 32, wn = (warp & 1) * 24;
    int bm0 = blockIdx.y * 64, bn0 = blockIdx.x * 48;
    int kb0 = blockIdx.z * NKBS;

    int ar = t >> 1, ak = (t & 1) * 8;
    int br = t / 6,  bs = t % 6;
    bool bact = t < 96;

    float acc[2][3][4];
    #pragma unroll
    for (int i = 0; i < 2; i++)
        #pragma unroll
        for (int j = 0; j < 3; j++)
            #pragma unroll
            for (int q = 0; q < 4; q++) acc[i][j][q] = 0.f;

    uint4 pAh, pAl, pBh, pBl;
    pBh = make_uint4(0,0,0,0); pBl = pBh;

    {
        int gr = bm0 + ar;
        if (gr < Nn) {
            size_t off = (size_t)gr * Nn + kb0 * 16 + ak;
            pAh = *(const uint4*)(Ah + off);
            pAl = *(const uint4*)(Al + off);
        } else { pAh = make_uint4(0,0,0,0); pAl = pAh; }
        if (bact) {
            size_t off = (size_t)(kb0 * 16 + br) * BCP + bn0 + bs * 8;
            pBh = *(const uint4*)(Bh + off);
            pBl = *(const uint4*)(Bl + off);
        }
        *(uint4*)&sAh[0][ar * ASTR + ak] = pAh;
        *(uint4*)&sAl[0][ar * ASTR + ak] = pAl;
        if (bact) {
            *(uint4*)&sBh[0][br * BSTR + bs * 8] = pBh;
            *(uint4*)&sBl[0][br * BSTR + bs * 8] = pBl;
        }
    }
    __syncthreads();

    uintT aoff = ((wm + (lane & 15)) * ASTR + ((lane & 16) ? 8 : 0)) * 2;
    uintT boff = ((lane & 15) * BSTR + wn) * 2;
    uintT baseAh0 = (uintT)__cvta_generic_to_shared(&sAh[0][0]);
    uintT baseAl0 = (uintT)__cvta_generic_to_shared(&sAl[0][0]);
    uintT baseBh0 = (uintT)__cvta_generic_to_shared(&sBh[0][0]);
    uintT baseBl0 = (uintT)__cvta_generic_to_shared(&sBl[0][0]);
    constexpr uintT abufB = 64 * ASTR * 2;
    constexpr uintT bbufB = 16 * BSTR * 2;

    for (int kb = 0; kb < NKBS; kb++) {
        int cur = kb & 1;
        if (kb < NKBS - 1) {
            int gr = bm0 + ar;
            if (gr < Nn) {
                size_t off = (size_t)gr * Nn + (kb0 + kb + 1) * 16 + ak;
                pAh = *(const uint4*)(Ah + off);
                pAl = *(const uint4*)(Al + off);
            } else { pAh = make_uint4(0,0,0,0); pAl = pAh; }
            if (bact) {
                size_t off = (size_t)((kb0 + kb + 1) * 16 + br) * BCP + bn0 + bs * 8;
                pBh = *(const uint4*)(Bh + off);
                pBl = *(const uint4*)(Bl + off);
            }
        }
        uintT fah[2][4], fal[2][4], fbh[3][2], fbl[3][2];
        #pragma unroll
        for (int mt = 0; mt < 2; mt++) {
            ldsm_x4(fah[mt], baseAh0 + cur * abufB + aoff + mt * 16 * ASTR * 2);
            ldsm_x4(fal[mt], baseAl0 + cur * abufB + aoff + mt * 16 * ASTR * 2);
        }
        #pragma unroll
        for (int nt = 0; nt < 3; nt++) {
            ldsm_x2t(fbh[nt], baseBh0 + cur * bbufB + boff + nt * 16);
            ldsm_x2t(fbl[nt], baseBl0 + cur * bbufB + boff + nt * 16);
        }
        #pragma unroll
        for (int mt = 0; mt < 2; mt++)
            #pragma unroll
            for (int nt = 0; nt < 3; nt++) {
                mma16816(acc[mt][nt], fah[mt], fbh[nt]);
                mma16816(acc[mt][nt], fah[mt], fbl[nt]);
                mma16816(acc[mt][nt], fal[mt], fbh[nt]);
            }
        __syncthreads();
        if (kb < NKBS - 1) {
            int nxt = cur ^ 1;
            *(uint4*)&sAh[nxt][ar * ASTR + ak] = pAh;
            *(uint4*)&sAl[nxt][ar * ASTR + ak] = pAl;
            if (bact) {
                *(uint4*)&sBh[nxt][br * BSTR + bs * 8] = pBh;
                *(uint4*)&sBl[nxt][br * BSTR + bs * 8] = pBl;
            }
            __syncthreads();
        }
    }
    float* Cp = g_Cpart + (size_t)blockIdx.z * Nn * BCP;
    #pragma unroll
    for (int mt = 0; mt < 2; mt++)
        #pragma unroll
        for (int nt = 0; nt < 3; nt++) {
            int row = bm0 + wm + mt * 16 + (lane >> 2);
            int col = bn0 + wn + nt * 8 + (lane & 3) * 2;
            if (row < Nn)
                *(float2*)&Cp[(size_t)row * BCP + col] = make_float2(acc[mt][nt][0], acc[mt][nt][1]);
            if (row + 8 < Nn)
                *(float2*)&Cp[(size_t)(row + 8) * BCP + col] = make_float2(acc[mt][nt][2], acc[mt][nt][3]);
        }
}

// ---------------- reduce split-K partials -> R1 fp32 + scaled bf16 hi/lo ----------------
__global__ void k_reduce1() {
    int i4 = blockIdx.x * 256 + threadIdx.x;
    if (i4 >= Nn * BCP / 4) return;
    float4 s = make_float4(0.f, 0.f, 0.f, 0.f);
    #pragma unroll
    for (int sp = 0; sp < KSP; sp++) {
        float4 p = ((const float4*)g_Cpart)[(size_t)sp * (Nn * BCP / 4) + i4];
        s.x += p.x; s.y += p.y; s.z += p.z; s.w += p.w;
    }
    ((float4*)g_R1)[i4] = s;
    int m = (i4 * 4) / BCP;
    float ci = g_cinv[m];
    float v[4] = { s.x * ci, s.y * ci, s.z * ci, s.w * ci };
    ushort4 hh, ll;
    ushortT* hp = &hh.x; ushortT* lp = &ll.x;
    #pragma unroll
    for (int q = 0; q < 4; q++) {
        ushortT h = f2bf(v[q]);
        hp[q] = h;
        lp[q] = f2bf(v[q] - bf2f(h));
    }
    ((ushort4*)g_R1h)[i4] = hh;
    ((ushort4*)g_R1l)[i4] = ll;
}

// ---------------- reduce split-K partials -> R2 fp32 ----------------
__global__ void k_reduce2() {
    int i4 = blockIdx.x * 256 + threadIdx.x;
    if (i4 >= Nn * BCP / 4) return;
    float4 s = make_float4(0.f, 0.f, 0.f, 0.f);
    #pragma unroll
    for (int sp = 0; sp < KSP; sp++) {
        float4 p = ((const float4*)g_Cpart)[(size_t)sp * (Nn * BCP / 4) + i4];
        s.x += p.x; s.y += p.y; s.z += p.z; s.w += p.w;
    }
    ((float4*)g_R2)[i4] = s;
}

// ---------------- node projections ----------------
__global__ void k_proj(const float* __restrict__ ne, const float* __restrict__ pool,
                       int cols, int mode) {
    __shared__ float p_s[16][256];
    __shared__ float ne_s[16][17];
    int n0 = blockIdx.x * 16;
    int c0 = blockIdx.y * 256;
    int t = threadIdx.x;
    for (int d = 0; d < 16; d++)
        p_s[d][t] = (c0 + t < cols) ? pool[(size_t)d * cols + c0 + t] : 0.f;
    { int nn = t >> 4, d = t & 15; ne_s[nn][d] = (n0 + nn < Nn) ? ne[(n0 + nn) * 16 + d] : 0.f; }
    __syncthreads();
    int c = c0 + t;
    if (c >= cols) return;
    float* outp = (mode == 0) ? g_W : (mode == 1) ? g_bias : (mode == 2) ? g_wwt : g_wws;
    for (int nn = 0; nn < 16; nn++) {
        if (n0 + nn >= Nn) break;
        float acc = 0.f;
        #pragma unroll
        for (int d = 0; d < 16; d++) acc += ne_s[nn][d] * p_s[d][t];
        outp[(size_t)(n0 + nn) * cols + c] = acc;
    }
}

// ---------------- gnn_w row sums ----------------
__global__ void k_rs(const float* __restrict__ gnn_w) {
    __shared__ float red[8];
    int m = blockIdx.x, t = threadIdx.x;
    float s = 0.f;
    for (int j = t; j < Nn; j += 256) s += gnn_w[(size_t)m * Nn + j];
    s = blk_sum(s, red);
    if (t == 0) g_rs[m] = s;
}

// ---------------- U,V from bootstrap-gathered xe ----------------
__global__ void k_uv(const float* __restrict__ xew, const int* __restrict__ bidx,
                     const float* __restrict__ lw, const float* __restrict__ lb) {
    int idx = blockIdx.x * 256 + threadIdx.x;
    if (idx >= Bb * Ee) return;
    int b = idx / Ee, i = idx % Ee;
    float w = lw[0], bia = lb[0];
    float u = 0.f, v = 0.f;
    #pragma unroll
    for (int f = 0; f < NBt; f++) {
        int tt = bidx[f]; tt = max(0, min(Ww - 1, tt));
        float xv = xew[((size_t)(b * Ww + tt)) * Ee + i] * w + bia;
        u += xv; v += (float)(NBt - 1 - f) * xv;
    }
    g_U[idx] = u; g_V[idx] = v;
}

// ---------------- hodge partials ----------------
__global__ void k_hodge(const float* __restrict__ hodge) {
    __shared__ float u_s[16][192];
    constexpr int CL = (Ee + HCH - 1) / HCH; // 188
    int ch = blockIdx.y;
    int i0 = ch * CL;
    int ilen = min(CL, Ee - i0);
    int t = threadIdx.x;
    for (int idx = t; idx < Bb * ilen; idx += 256) {
        int bb = idx / ilen, ii = idx % ilen;
        u_s[bb][ii] = g_U[bb * Ee + i0 + ii];
    }
    __syncthreads();
    int j = blockIdx.x * 256 + t;
    if (j >= Ee) return;
    float acc[16];
    #pragma unroll
    for (int bb = 0; bb < 16; bb++) acc[bb] = 0.f;
    for (int ii = 0; ii < ilen; ii++) {
        float h = hodge[(size_t)(i0 + ii) * Ee + j];
        #pragma unroll
        for (int bb = 0; bb < 16; bb++) acc[bb] += u_s[bb][ii] * h;
    }
    #pragma unroll
    for (int bb = 0; bb < 16; bb++)
        g_Hpart[((size_t)ch * Bb + bb) * Ee + j] = acc[bb];
}

__global__ void k_ybar(const void* p_jump) {
    int idx = blockIdx.x * 256 + threadIdx.x;
    if (idx >= Bb * Ee) return;
    int b = idx / Ee, j = idx % Ee;
    float jump = scalar_val(p_jump);
    float s = jump * g_V[idx];
    #pragma unroll
    for (int ch = 0; ch < HCH; ch++) s += g_Hpart[((size_t)ch * Bb + b) * Ee + j];
    g_Ybar[idx] = s * (1.f / (float)NBt);
}

// ---------------- Mpart[sp,b,n] = sum_{e in split} Ybar[b,e]*inc[n,e] ----------------
__global__ void k_m(const float* __restrict__ inc) {
    __shared__ float inc_s[32][65];
    __shared__ float yb_s[16][64];
    constexpr int SL = Ee / MKS; // 750
    int n0 = blockIdx.x * 32;
    int sp = blockIdx.y;
    int e_start = sp * SL, e_end = e_start + SL;
    int t = threadIdx.x;
    int nl = t & 31, bg = t >> 5;
    int b0 = bg * 2, b1 = bg * 2 + 1;
    float acc0 = 0.f, acc1 = 0.f;
    for (int e0 = e_start; e0 < e_end; e0 += 64) {
        for (int idx = t; idx < 32 * 64; idx += 256) {
            int r = idx >> 6, c = idx & 63;
            int n = n0 + r, e = e0 + c;
            inc_s[r][c] = (n < Nn && e < e_end) ? inc[(size_t)n * Ee + e] : 0.f;
        }
        for (int idx = t; idx < 16 * 64; idx += 256) {
            int bb = idx >> 6, c = idx & 63;
            int e = e0 + c;
            yb_s[bb][c] = (e < e_end) ? g_Ybar[bb * Ee + e] : 0.f;
        }
        __syncthreads();
        #pragma unroll
        for (int c = 0; c < 64; c++) {
            float w = inc_s[nl][c];
            acc0 += yb_s[b0][c] * w;
            acc1 += yb_s[b1][c] * w;
        }
        __syncthreads();
    }
    int n = n0 + nl;
    if (n < Nn) {
        g_Mpart[((size_t)sp * Bb + b0) * Nn + n] = acc0;
        g_Mpart[((size_t)sp * Bb + b1) * Nn + n] = acc1;
    }
}

// ---------------- XW[b,n] = sum_t x_window[b,t,n]*Tp[t] ----------------
__global__ void k_xw(const float* __restrict__ xwin, const float* __restrict__ Tp) {
    int idx = blockIdx.x * 256 + threadIdx.x;
    if (idx >= Bb * Nn) return;
    int b = idx / Nn, n = idx % Nn;
    float s = 0.f;
    #pragma unroll
    for (int t = 0; t < Ww; t++) s += xwin[((size_t)(b * Ww + t)) * Nn + n] * Tp[t];
    g_XW[idx] = s;
}

// ---------------- fused assembly ----------------
__global__ void k_assembly(const float* __restrict__ x, const float* __restrict__ zfc_in,
                           const float* __restrict__ gnn_b, float* __restrict__ out) {
    __shared__ float xs_s[16][52];
    __shared__ float zfc_s[16][32];
    __shared__ float xw_s[16];
    __shared__ float m_s[16];
    int n = blockIdx.x;
    int t = threadIdx.x;
    for (int idx = t; idx < Bb * KC; idx += 256) {
        int b = idx / KC, ki = idx % KC;
        int k = ki / Cc, c = ki % Cc;
        float v;
        if (k == 0)      v = x[((size_t)b * Nn + n) * Cc + c];
        else if (k == 1) v = g_R1[(size_t)n * BCP + b * Cc + c];
        else             v = g_R2[(size_t)n * BCP + b * Cc + c];
        xs_s[b][ki] = v;
    }
    for (int idx = t; idx < Bb * 32; idx += 256)
        zfc_s[idx >> 5][idx & 31] = zfc_in[idx];
    if (t < 16) {
        xw_s[t] = g_XW[t * Nn + n];
        float ms = 0.f;
        #pragma unroll
        for (int sp = 0; sp < MKS; sp++) ms += g_Mpart[((size_t)sp * Bb + t) * Nn + n];
        m_s[t] = ms;
    }
    __syncthreads();

    int o = t;
    float biasv = g_bias[(size_t)n * Oo + o];
    if (o < 64) {
        float w[KC];
        #pragma unroll
        for (int ki = 0; ki < KC; ki++) w[ki] = g_W[(size_t)n * WCOLS + ki * 64 + o];
        for (int b = 0; b < 16; b++) {
            float acc = 0.f;
            #pragma unroll
            for (int ki = 0; ki < KC; ki++) acc += xs_s[b][ki] * w[ki];
            out[((size_t)b * Nn + n) * Oo + o] = acc + biasv;
        }
    } else if (o < 96) {
        int c = o - 64;
        int flat = n * 32 + c;
        int r = flat / Nn;
        int m = flat - r * Nn;
        float rsv = g_rs[m], gb = gnn_b[m];
        for (int b = 0; b < 16; b++) {
            float v = fmaxf(zfc_s[b][r] * rsv + gb, 0.f);
            out[((size_t)b * Nn + n) * Oo + o] = v + biasv;
        }
    } else if (o < 224) {
        float wv = g_wwt[(size_t)n * 128 + (o - 96)];
        for (int b = 0; b < 16; b++)
            out[((size_t)b * Nn + n) * Oo + o] = xw_s[b] * wv + biasv;
    } else {
        float wv = g_wws[(size_t)n * 32 + (o - 224)];
        for (int b = 0; b < 16; b++)
            out[((size_t)b * Nn + n) * Oo + o] = m_s[b] * wv + biasv;
    }
}

// ---------------- host launch ----------------
extern "C" void kernel_launch(void* const* d_in, const int* in_sizes, int n_in,
                              void* d_out, int out_size) {
    const float* x     = (const float*)d_in[0];
    const float* xwin  = (const float*)d_in[1];
    const float* ne    = (const float*)d_in[2];
    const void*  p_fix = d_in[3];
    const float* adj   = (const float*)d_in[4];
    const void*  p_sty = d_in[5];
    const void*  p_jmp = d_in[6];
    const float* zfc   = (const float*)d_in[7];
    const float* hodge = (const float*)d_in[8];
    const float* xew   = (const float*)d_in[9];
    const float* inc   = (const float*)d_in[10];
    const float* wp    = (const float*)d_in[11];
    const float* wws_p = (const float*)d_in[12];
    const float* wwt_p = (const float*)d_in[13];
    const float* bp    = (const float*)d_in[14];
    const float* Tp    = (const float*)d_in[15];
    const float* lw    = (const float*)d_in[16];
    const float* lb    = (const float*)d_in[17];
    const float* gnn_w = (const float*)d_in[18];
    const float* gnn_b = (const float*)d_in[19];
    const int*   bidx  = (const int*)d_in[20];
    float* out = (float*)d_out;

    static ushortT *pSh = nullptr, *pSl, *pXh, *pXl, *pR1h, *pR1l;
    if (!pSh) {
        cudaGetSymbolAddress((void**)&pSh,  g_Sh);
        cudaGetSymbolAddress((void**)&pSl,  g_Sl);
        cudaGetSymbolAddress((void**)&pXh,  g_Xh);
        cudaGetSymbolAddress((void**)&pXl,  g_Xl);
        cudaGetSymbolAddress((void**)&pR1h, g_R1h);
        cudaGetSymbolAddress((void**)&pR1l, g_R1l);
    }

    // S pipeline; GEMM1 placed 4th so the -s 5 profile lands on it
    k_s0<<<dim3(125, 125), 256>>>(ne, p_sty);                      // 1
    k_softmax_split<<<Nn, 256>>>(p_fix, adj);                      // 2
    k_splitX<<<(Nn * BCP + 255) / 256, 256>>>(x);                  // 3
    k_mmagemm<<<dim3(6, 32, KSP), 128>>>(pSh, pSl, pXh, pXl);      // 4: partials of S' @ X
    k_reduce1<<<(Nn * BCP / 4 + 255) / 256, 256>>>();              // 5: R1 + scaled bf16
    k_mmagemm<<<dim3(6, 32, KSP), 128>>>(pSh, pSl, pR1h, pR1l);    // 6: partials of S' @ R1'
    k_reduce2<<<(Nn * BCP / 4 + 255) / 256, 256>>>();              // 7: R2

    // independent branches
    k_proj<<<dim3(125, 13), 256>>>(ne, wp, WCOLS, 0);
    k_proj<<<dim3(125, 1), 256>>>(ne, bp, Oo, 1);
    k_proj<<<dim3(125, 1), 256>>>(ne, wwt_p, 128, 2);
    k_proj<<<dim3(125, 1), 256>>>(ne, wws_p, 32, 3);
    k_rs<<<Nn, 256>>>(gnn_w);
    k_uv<<<(Bb * Ee + 255) / 256, 256>>>(xew, bidx, lw, lb);
    k_hodge<<<dim3((Ee + 255) / 256, HCH), 256>>>(hodge);
    k_ybar<<<(Bb * Ee + 255) / 256, 256>>>(p_jmp);
    k_m<<<dim3((Nn + 31) / 32, MKS), 256>>>(inc);
    k_xw<<<(Bb * Nn + 255) / 256, 256>>>(xwin, Tp);

    // fused output
    k_assembly<<<Nn, 256>>>(x, zfc, gnn_b, out);
}

// round 5
// speedup vs baseline: 2.0581x; 1.2342x over previous
#include <cuda_runtime.h>
#include <cuda_bf16.h>
#include <math.h>

typedef unsigned short ushortT;
typedef unsigned int uintT;

// ---------------- problem dims ----------------
constexpr int Bb = 16, Nn = 2000, Ee = 3000, Cc = 17, Ww = 12, Dd = 16, Oo = 256, Kk = 3, NBt = 3;
constexpr int BCP   = 288;           // padded packed columns (272 valid)
constexpr int KC    = Kk * Cc;       // 51
constexpr int WCOLS = KC * 64;       // 3264
constexpr int HCH   = 16;            // hodge K-split chunks
constexpr int MKS   = 4;             // inc GEMM K-splits
constexpr int KSP   = 5;             // GEMM split-K factor
constexpr int NKBS  = 25;            // k-blocks per split

// ---------------- scratch (device globals, no allocation) ----------------
__device__ __align__(16) float  g_cinv[Nn];
__device__ __align__(16) ushortT g_Sh[Nn * Nn];
__device__ __align__(16) ushortT g_Sl[Nn * Nn];
__device__ __align__(16) ushortT g_Xh[Nn * BCP];
__device__ __align__(16) ushortT g_Xl[Nn * BCP];
__device__ __align__(16) ushortT g_R1h[Nn * BCP];
__device__ __align__(16) ushortT g_R1l[Nn * BCP];
__device__ __align__(16) float  g_R1[Nn * BCP];
__device__ __align__(16) float  g_R2[Nn * BCP];
__device__ __align__(16) float  g_Cpart[KSP * Nn * BCP];
__device__ float g_W   [Nn * WCOLS];
__device__ float g_bias[Nn * Oo];
__device__ float g_wwt [Nn * 128];
__device__ float g_wws [Nn * 32];
__device__ float g_U[Bb * Ee];
__device__ float g_V[Bb * Ee];
__device__ float g_Hpart[HCH * Bb * Ee];
__device__ float g_Ybar[Bb * Ee];
__device__ float g_Mpart[MKS * Bb * Nn];
__device__ float g_XW[Bb * Nn];
__device__ float g_rs[Nn];

__device__ __forceinline__ float scalar_val(const void* p) {
    int v = *(const int*)p;
    if (v > -100000000 && v < 100000000) return (float)v;
    return __int_as_float(v);
}
__device__ __forceinline__ ushortT f2bf(float v) {
    __nv_bfloat16 b = __float2bfloat16(v);
    return *reinterpret_cast<ushortT*>(&b);
}
__device__ __forceinline__ float bf2f(ushortT u) {
    __nv_bfloat16 b; *reinterpret_cast<ushortT*>(&b) = u;
    return __bfloat162float(b);
}

__device__ __forceinline__ float blk_max(float v, float* red) {
    #pragma unroll
    for (int o = 16; o > 0; o >>= 1) v = fmaxf(v, __shfl_xor_sync(0xffffffffu, v, o));
    int t = threadIdx.x;
    if ((t & 31) == 0) red[t >> 5] = v;
    __syncthreads();
    if (t < 8) {
        v = red[t];
        #pragma unroll
        for (int o = 4; o > 0; o >>= 1) v = fmaxf(v, __shfl_xor_sync(0xffu, v, o));
        if (t == 0) red[0] = v;
    }
    __syncthreads();
    v = red[0];
    __syncthreads();
    return v;
}
__device__ __forceinline__ float blk_sum(float v, float* red) {
    #pragma unroll
    for (int o = 16; o > 0; o >>= 1) v += __shfl_xor_sync(0xffffffffu, v, o);
    int t = threadIdx.x;
    if ((t & 31) == 0) red[t >> 5] = v;
    __syncthreads();
    if (t < 8) {
        v = red[t];
        #pragma unroll
        for (int o = 4; o > 0; o >>= 1) v += __shfl_xor_sync(0xffu, v, o);
        if (t == 0) red[0] = v;
    }
    __syncthreads();
    v = red[0];
    __syncthreads();
    return v;
}

// ---------------- fused: S0 = relu(ne@ne^T) diag=stay -> row softmax -> bf16 split ----------------
// One CTA per 16-row strip; strip kept in dynamic smem (16*2000 floats).
__global__ void __launch_bounds__(256) k_sfused(const float* __restrict__ ne,
                                                const void* p_stay, const void* p_fixed,
                                                const float* __restrict__ adj) {
    extern __shared__ float strip[];             // [16][Nn]
    __shared__ float neI[16][16];
    __shared__ float red[8];
    int i0 = blockIdx.x * 16;
    int t = threadIdx.x;
    neI[t >> 4][t & 15] = ne[(i0 + (t >> 4)) * Dd + (t & 15)];
    __syncthreads();
    bool fixed = (scalar_val(p_fixed) != 0.f);
    float stay = scalar_val(p_stay);
    for (int j = t; j < Nn; j += 256) {
        float nj[16];
        const float4* njp = (const float4*)&ne[j * Dd];
        #pragma unroll
        for (int q = 0; q < 4; q++) {
            float4 v = njp[q];
            nj[q*4+0] = v.x; nj[q*4+1] = v.y; nj[q*4+2] = v.z; nj[q*4+3] = v.w;
        }
        #pragma unroll
        for (int r = 0; r < 16; r++) {
            float acc = 0.f;
            #pragma unroll
            for (int d = 0; d < 16; d++) acc += neI[r][d] * nj[d];
            acc = fmaxf(acc, 0.f);
            if (i0 + r == j) acc = stay;
            strip[r * Nn + j] = acc;
        }
    }
    __syncthreads();
    for (int r = 0; r < 16; r++) {
        size_t rowoff = (size_t)(i0 + r) * Nn;
        float* row = &strip[r * Nn];
        float outsum;
        if (!fixed) {
            float m = -1e30f;
            for (int j = t; j < Nn; j += 256) m = fmaxf(m, row[j]);
            m = blk_max(m, red);
            float s = 0.f;
            for (int j = t; j < Nn; j += 256) { float e = __expf(row[j] - m); row[j] = e; s += e; }
            s = blk_sum(s, red);
            float inv = 1.f / s;
            float fs = 0.f;
            for (int j = t; j < Nn; j += 256) {
                float v = row[j] * inv;
                ushortT h = f2bf(v);
                g_Sh[rowoff + j] = h;
                g_Sl[rowoff + j] = f2bf(v - bf2f(h));
                fs += v;
            }
            outsum = blk_sum(fs, red);
        } else {
            float fs = 0.f;
            for (int j = t; j < Nn; j += 256) {
                float v = adj[rowoff + j] * __expf(row[j]);
                ushortT h = f2bf(v);
                g_Sh[rowoff + j] = h;
                g_Sl[rowoff + j] = f2bf(v - bf2f(h));
                fs += v;
            }
            outsum = blk_sum(fs, red);
        }
        if (t == 0) g_cinv[i0 + r] = 1.f / outsum;
    }
}

// ---------------- x (B,N,C) -> bf16 hi/lo packed [m][288], row-scaled by cinv ----------------
__global__ void k_splitX(const float* __restrict__ x) {
    int idx = blockIdx.x * 256 + threadIdx.x;
    if (idx >= Nn * BCP) return;
    int m = idx / BCP, q = idx % BCP;
    float v = 0.f;
    if (q < Bb * Cc) {
        int b = q / Cc, c = q % Cc;
        v = x[((size_t)b * Nn + m) * Cc + c] * g_cinv[m];
    }
    ushortT h = f2bf(v);
    g_Xh[idx] = h;
    g_Xl[idx] = f2bf(v - bf2f(h));
}

// ---------------- split-K tensor-core GEMM partials ----------------
__device__ __forceinline__ void ldsm_x4(uintT* r, uintT addr) {
    asm volatile("ldmatrix.sync.aligned.m8n8.x4.shared.b16 {%0,%1,%2,%3}, [%4];"
                 : "=r"(r[0]), "=r"(r[1]), "=r"(r[2]), "=r"(r[3]) : "r"(addr));
}
__device__ __forceinline__ void ldsm_x2t(uintT* r, uintT addr) {
    asm volatile("ldmatrix.sync.aligned.m8n8.x2.trans.shared.b16 {%0,%1}, [%2];"
                 : "=r"(r[0]), "=r"(r[1]) : "r"(addr));
}
__device__ __forceinline__ void mma16816(float* c, const uintT* a, const uintT* b) {
    asm volatile("mma.sync.aligned.m16n8k16.row.col.f32.bf16.bf16.f32 "
                 "{%0,%1,%2,%3}, {%4,%5,%6,%7}, {%8,%9}, {%0,%1,%2,%3};"
                 : "+f"(c[0]), "+f"(c[1]), "+f"(c[2]), "+f"(c[3])
                 : "r"(a[0]), "r"(a[1]), "r"(a[2]), "r"(a[3]), "r"(b[0]), "r"(b[1]));
}

__global__ void __launch_bounds__(128) k_mmagemm(
        const ushortT* __restrict__ Ah, const ushortT* __restrict__ Al,
        const ushortT* __restrict__ Bh, const ushortT* __restrict__ Bl) {
    constexpr int ASTR = 24;
    constexpr int BSTR = 56;
    __shared__ ushortT sAh[2][64 * ASTR], sAl[2][64 * ASTR];
    __shared__ ushortT sBh[2][16 * BSTR], sBl[2][16 * BSTR];

    int t = threadIdx.x;
    int warp = t >> 5, lane = t & 31;
    int wm = (warp >> 1) * 32, wn = (warp & 1) * 24;
    int bm0 = blockIdx.y * 64, bn0 = blockIdx.x * 48;
    int kb0 = blockIdx.z * NKBS;

    int ar = t >> 1, ak = (t & 1) * 8;
    int br = t / 6,  bs = t % 6;
    bool bact = t < 96;

    float acc[2][3][4];
    #pragma unroll
    for (int i = 0; i < 2; i++)
        #pragma unroll
        for (int j = 0; j < 3; j++)
            #pragma unroll
            for (int q = 0; q < 4; q++) acc[i][j][q] = 0.f;

    uint4 pAh, pAl, pBh, pBl;
    pBh = make_uint4(0,0,0,0); pBl = pBh;

    {
        int gr = bm0 + ar;
        if (gr < Nn) {
            size_t off = (size_t)gr * Nn + kb0 * 16 + ak;
            pAh = *(const uint4*)(Ah + off);
            pAl = *(const uint4*)(Al + off);
        } else { pAh = make_uint4(0,0,0,0); pAl = pAh; }
        if (bact) {
            size_t off = (size_t)(kb0 * 16 + br) * BCP + bn0 + bs * 8;
            pBh = *(const uint4*)(Bh + off);
            pBl = *(const uint4*)(Bl + off);
        }
        *(uint4*)&sAh[0][ar * ASTR + ak] = pAh;
        *(uint4*)&sAl[0][ar * ASTR + ak] = pAl;
        if (bact) {
            *(uint4*)&sBh[0][br * BSTR + bs * 8] = pBh;
            *(uint4*)&sBl[0][br * BSTR + bs * 8] = pBl;
        }
    }
    __syncthreads();

    uintT aoff = ((wm + (lane & 15)) * ASTR + ((lane & 16) ? 8 : 0)) * 2;
    uintT boff = ((lane & 15) * BSTR + wn) * 2;
    uintT baseAh0 = (uintT)__cvta_generic_to_shared(&sAh[0][0]);
    uintT baseAl0 = (uintT)__cvta_generic_to_shared(&sAl[0][0]);
    uintT baseBh0 = (uintT)__cvta_generic_to_shared(&sBh[0][0]);
    uintT baseBl0 = (uintT)__cvta_generic_to_shared(&sBl[0][0]);
    constexpr uintT abufB = 64 * ASTR * 2;
    constexpr uintT bbufB = 16 * BSTR * 2;

    for (int kb = 0; kb < NKBS; kb++) {
        int cur = kb & 1;
        if (kb < NKBS - 1) {
            int gr = bm0 + ar;
            if (gr < Nn) {
                size_t off = (size_t)gr * Nn + (kb0 + kb + 1) * 16 + ak;
                pAh = *(const uint4*)(Ah + off);
                pAl = *(const uint4*)(Al + off);
            } else { pAh = make_uint4(0,0,0,0); pAl = pAh; }
            if (bact) {
                size_t off = (size_t)((kb0 + kb + 1) * 16 + br) * BCP + bn0 + bs * 8;
                pBh = *(const uint4*)(Bh + off);
                pBl = *(const uint4*)(Bl + off);
            }
        }
        uintT fah[2][4], fal[2][4], fbh[3][2], fbl[3][2];
        #pragma unroll
        for (int mt = 0; mt < 2; mt++) {
            ldsm_x4(fah[mt], baseAh0 + cur * abufB + aoff + mt * 16 * ASTR * 2);
            ldsm_x4(fal[mt], baseAl0 + cur * abufB + aoff + mt * 16 * ASTR * 2);
        }
        #pragma unroll
        for (int nt = 0; nt < 3; nt++) {
            ldsm_x2t(fbh[nt], baseBh0 + cur * bbufB + boff + nt * 16);
            ldsm_x2t(fbl[nt], baseBl0 + cur * bbufB + boff + nt * 16);
        }
        #pragma unroll
        for (int mt = 0; mt < 2; mt++)
            #pragma unroll
            for (int nt = 0; nt < 3; nt++) {
                mma16816(acc[mt][nt], fah[mt], fbh[nt]);
                mma16816(acc[mt][nt], fah[mt], fbl[nt]);
                mma16816(acc[mt][nt], fal[mt], fbh[nt]);
            }
        __syncthreads();
        if (kb < NKBS - 1) {
            int nxt = cur ^ 1;
            *(uint4*)&sAh[nxt][ar * ASTR + ak] = pAh;
            *(uint4*)&sAl[nxt][ar * ASTR + ak] = pAl;
            if (bact) {
                *(uint4*)&sBh[nxt][br * BSTR + bs * 8] = pBh;
                *(uint4*)&sBl[nxt][br * BSTR + bs * 8] = pBl;
            }
            __syncthreads();
        }
    }
    float* Cp = g_Cpart + (size_t)blockIdx.z * Nn * BCP;
    #pragma unroll
    for (int mt = 0; mt < 2; mt++)
        #pragma unroll
        for (int nt = 0; nt < 3; nt++) {
            int row = bm0 + wm + mt * 16 + (lane >> 2);
            int col = bn0 + wn + nt * 8 + (lane & 3) * 2;
            if (row < Nn)
                *(float2*)&Cp[(size_t)row * BCP + col] = make_float2(acc[mt][nt][0], acc[mt][nt][1]);
            if (row + 8 < Nn)
                *(float2*)&Cp[(size_t)(row + 8) * BCP + col] = make_float2(acc[mt][nt][2], acc[mt][nt][3]);
        }
}

// ---------------- reduce split-K partials -> R1 fp32 + scaled bf16 hi/lo ----------------
__global__ void k_reduce1() {
    int i4 = blockIdx.x * 256 + threadIdx.x;
    if (i4 >= Nn * BCP / 4) return;
    float4 s = make_float4(0.f, 0.f, 0.f, 0.f);
    #pragma unroll
    for (int sp = 0; sp < KSP; sp++) {
        float4 p = ((const float4*)g_Cpart)[(size_t)sp * (Nn * BCP / 4) + i4];
        s.x += p.x; s.y += p.y; s.z += p.z; s.w += p.w;
    }
    ((float4*)g_R1)[i4] = s;
    int m = (i4 * 4) / BCP;
    float ci = g_cinv[m];
    float v[4] = { s.x * ci, s.y * ci, s.z * ci, s.w * ci };
    ushort4 hh, ll;
    ushortT* hp = &hh.x; ushortT* lp = &ll.x;
    #pragma unroll
    for (int q = 0; q < 4; q++) {
        ushortT h = f2bf(v[q]);
        hp[q] = h;
        lp[q] = f2bf(v[q] - bf2f(h));
    }
    ((ushort4*)g_R1h)[i4] = hh;
    ((ushort4*)g_R1l)[i4] = ll;
}

// ---------------- reduce split-K partials -> R2 fp32 ----------------
__global__ void k_reduce2() {
    int i4 = blockIdx.x * 256 + threadIdx.x;
    if (i4 >= Nn * BCP / 4) return;
    float4 s = make_float4(0.f, 0.f, 0.f, 0.f);
    #pragma unroll
    for (int sp = 0; sp < KSP; sp++) {
        float4 p = ((const float4*)g_Cpart)[(size_t)sp * (Nn * BCP / 4) + i4];
        s.x += p.x; s.y += p.y; s.z += p.z; s.w += p.w;
    }
    ((float4*)g_R2)[i4] = s;
}

// ---------------- node projections ----------------
__global__ void k_proj(const float* __restrict__ ne, const float* __restrict__ pool,
                       int cols, int mode) {
    __shared__ float p_s[16][256];
    __shared__ float ne_s[16][17];
    int n0 = blockIdx.x * 16;
    int c0 = blockIdx.y * 256;
    int t = threadIdx.x;
    for (int d = 0; d < 16; d++)
        p_s[d][t] = (c0 + t < cols) ? pool[(size_t)d * cols + c0 + t] : 0.f;
    { int nn = t >> 4, d = t & 15; ne_s[nn][d] = (n0 + nn < Nn) ? ne[(n0 + nn) * 16 + d] : 0.f; }
    __syncthreads();
    int c = c0 + t;
    if (c >= cols) return;
    float* outp = (mode == 0) ? g_W : (mode == 1) ? g_bias : (mode == 2) ? g_wwt : g_wws;
    for (int nn = 0; nn < 16; nn++) {
        if (n0 + nn >= Nn) break;
        float acc = 0.f;
        #pragma unroll
        for (int d = 0; d < 16; d++) acc += ne_s[nn][d] * p_s[d][t];
        outp[(size_t)(n0 + nn) * cols + c] = acc;
    }
}

// ---------------- gnn_w row sums ----------------
__global__ void k_rs(const float* __restrict__ gnn_w) {
    __shared__ float red[8];
    int m = blockIdx.x, t = threadIdx.x;
    float s = 0.f;
    for (int j = t; j < Nn; j += 256) s += gnn_w[(size_t)m * Nn + j];
    s = blk_sum(s, red);
    if (t == 0) g_rs[m] = s;
}

// ---------------- U,V from bootstrap-gathered xe ----------------
__global__ void k_uv(const float* __restrict__ xew, const int* __restrict__ bidx,
                     const float* __restrict__ lw, const float* __restrict__ lb) {
    int idx = blockIdx.x * 256 + threadIdx.x;
    if (idx >= Bb * Ee) return;
    int b = idx / Ee, i = idx % Ee;
    float w = lw[0], bia = lb[0];
    float u = 0.f, v = 0.f;
    #pragma unroll
    for (int f = 0; f < NBt; f++) {
        int tt = bidx[f]; tt = max(0, min(Ww - 1, tt));
        float xv = xew[((size_t)(b * Ww + tt)) * Ee + i] * w + bia;
        u += xv; v += (float)(NBt - 1 - f) * xv;
    }
    g_U[idx] = u; g_V[idx] = v;
}

// ---------------- hodge partials ----------------
__global__ void k_hodge(const float* __restrict__ hodge) {
    __shared__ float u_s[16][192];
    constexpr int CL = (Ee + HCH - 1) / HCH; // 188
    int ch = blockIdx.y;
    int i0 = ch * CL;
    int ilen = min(CL, Ee - i0);
    int t = threadIdx.x;
    for (int idx = t; idx < Bb * ilen; idx += 256) {
        int bb = idx / ilen, ii = idx % ilen;
        u_s[bb][ii] = g_U[bb * Ee + i0 + ii];
    }
    __syncthreads();
    int j = blockIdx.x * 256 + t;
    if (j >= Ee) return;
    float acc[16];
    #pragma unroll
    for (int bb = 0; bb < 16; bb++) acc[bb] = 0.f;
    for (int ii = 0; ii < ilen; ii++) {
        float h = hodge[(size_t)(i0 + ii) * Ee + j];
        #pragma unroll
        for (int bb = 0; bb < 16; bb++) acc[bb] += u_s[bb][ii] * h;
    }
    #pragma unroll
    for (int bb = 0; bb < 16; bb++)
        g_Hpart[((size_t)ch * Bb + bb) * Ee + j] = acc[bb];
}

__global__ void k_ybar(const void* p_jump) {
    int idx = blockIdx.x * 256 + threadIdx.x;
    if (idx >= Bb * Ee) return;
    int b = idx / Ee, j = idx % Ee;
    float jump = scalar_val(p_jump);
    float s = jump * g_V[idx];
    #pragma unroll
    for (int ch = 0; ch < HCH; ch++) s += g_Hpart[((size_t)ch * Bb + b) * Ee + j];
    g_Ybar[idx] = s * (1.f / (float)NBt);
}

// ---------------- Mpart[sp,b,n] = sum_{e in split} Ybar[b,e]*inc[n,e] ----------------
__global__ void k_m(const float* __restrict__ inc) {
    __shared__ float inc_s[32][65];
    __shared__ float yb_s[16][64];
    constexpr int SL = Ee / MKS; // 750
    int n0 = blockIdx.x * 32;
    int sp = blockIdx.y;
    int e_start = sp * SL, e_end = e_start + SL;
    int t = threadIdx.x;
    int nl = t & 31, bg = t >> 5;
    int b0 = bg * 2, b1 = bg * 2 + 1;
    float acc0 = 0.f, acc1 = 0.f;
    for (int e0 = e_start; e0 < e_end; e0 += 64) {
        for (int idx = t; idx < 32 * 64; idx += 256) {
            int r = idx >> 6, c = idx & 63;
            int n = n0 + r, e = e0 + c;
            inc_s[r][c] = (n < Nn && e < e_end) ? inc[(size_t)n * Ee + e] : 0.f;
        }
        for (int idx = t; idx < 16 * 64; idx += 256) {
            int bb = idx >> 6, c = idx & 63;
            int e = e0 + c;
            yb_s[bb][c] = (e < e_end) ? g_Ybar[bb * Ee + e] : 0.f;
        }
        __syncthreads();
        #pragma unroll
        for (int c = 0; c < 64; c++) {
            float w = inc_s[nl][c];
            acc0 += yb_s[b0][c] * w;
            acc1 += yb_s[b1][c] * w;
        }
        __syncthreads();
    }
    int n = n0 + nl;
    if (n < Nn) {
        g_Mpart[((size_t)sp * Bb + b0) * Nn + n] = acc0;
        g_Mpart[((size_t)sp * Bb + b1) * Nn + n] = acc1;
    }
}

// ---------------- XW[b,n] = sum_t x_window[b,t,n]*Tp[t] ----------------
__global__ void k_xw(const float* __restrict__ xwin, const float* __restrict__ Tp) {
    int idx = blockIdx.x * 256 + threadIdx.x;
    if (idx >= Bb * Nn) return;
    int b = idx / Nn, n = idx % Nn;
    float s = 0.f;
    #pragma unroll
    for (int t = 0; t < Ww; t++) s += xwin[((size_t)(b * Ww + t)) * Nn + n] * Tp[t];
    g_XW[idx] = s;
}

// ---------------- diffusion assembly: output cols 0..63 ----------------
__global__ void k_asm_diff(const float* __restrict__ x, float* __restrict__ out) {
    __shared__ float xs_s[16][52];
    int n = blockIdx.x;
    int t = threadIdx.x;
    for (int idx = t; idx < Bb * KC; idx += 256) {
        int b = idx / KC, ki = idx % KC;
        int k = ki / Cc, c = ki % Cc;
        float v;
        if (k == 0)      v = x[((size_t)b * Nn + n) * Cc + c];
        else if (k == 1) v = g_R1[(size_t)n * BCP + b * Cc + c];
        else             v = g_R2[(size_t)n * BCP + b * Cc + c];
        xs_s[b][ki] = v;
    }
    __syncthreads();
    int o = t;
    if (o >= 64) return;
    float biasv = g_bias[(size_t)n * Oo + o];
    float w[KC];
    #pragma unroll
    for (int ki = 0; ki < KC; ki++) w[ki] = g_W[(size_t)n * WCOLS + ki * 64 + o];
    for (int b = 0; b < 16; b++) {
        float acc = 0.f;
        #pragma unroll
        for (int ki = 0; ki < KC; ki++) acc += xs_s[b][ki] * w[ki];
        out[((size_t)b * Nn + n) * Oo + o] = acc + biasv;
    }
}

// ---------------- rest assembly: output cols 64..255 ----------------
__global__ void k_asm_rest(const float* __restrict__ zfc_in, const float* __restrict__ gnn_b,
                           float* __restrict__ out) {
    __shared__ float zfc_s[16][32];
    __shared__ float xw_s[16];
    __shared__ float m_s[16];
    int n = blockIdx.x;
    int t = threadIdx.x;   // 0..191
    for (int idx = t; idx < Bb * 32; idx += 192)
        zfc_s[idx >> 5][idx & 31] = zfc_in[idx];
    if (t < 16) {
        xw_s[t] = g_XW[t * Nn + n];
        float ms = 0.f;
        #pragma unroll
        for (int sp = 0; sp < MKS; sp++) ms += g_Mpart[((size_t)sp * Bb + t) * Nn + n];
        m_s[t] = ms;
    }
    __syncthreads();
    int o = 64 + t;
    float biasv = g_bias[(size_t)n * Oo + o];
    if (o < 96) {
        int c = o - 64;
        int flat = n * 32 + c;
        int r = flat / Nn;
        int m = flat - r * Nn;
        float rsv = g_rs[m], gb = gnn_b[m];
        for (int b = 0; b < 16; b++) {
            float v = fmaxf(zfc_s[b][r] * rsv + gb, 0.f);
            out[((size_t)b * Nn + n) * Oo + o] = v + biasv;
        }
    } else if (o < 224) {
        float wv = g_wwt[(size_t)n * 128 + (o - 96)];
        for (int b = 0; b < 16; b++)
            out[((size_t)b * Nn + n) * Oo + o] = xw_s[b] * wv + biasv;
    } else {
        float wv = g_wws[(size_t)n * 32 + (o - 224)];
        for (int b = 0; b < 16; b++)
            out[((size_t)b * Nn + n) * Oo + o] = m_s[b] * wv + biasv;
    }
}

// ---------------- host launch ----------------
extern "C" void kernel_launch(void* const* d_in, const int* in_sizes, int n_in,
                              void* d_out, int out_size) {
    const float* x     = (const float*)d_in[0];
    const float* xwin  = (const float*)d_in[1];
    const float* ne    = (const float*)d_in[2];
    const void*  p_fix = d_in[3];
    const float* adj   = (const float*)d_in[4];
    const void*  p_sty = d_in[5];
    const void*  p_jmp = d_in[6];
    const float* zfc   = (const float*)d_in[7];
    const float* hodge = (const float*)d_in[8];
    const float* xew   = (const float*)d_in[9];
    const float* inc   = (const float*)d_in[10];
    const float* wp    = (const float*)d_in[11];
    const float* wws_p = (const float*)d_in[12];
    const float* wwt_p = (const float*)d_in[13];
    const float* bp    = (const float*)d_in[14];
    const float* Tp    = (const float*)d_in[15];
    const float* lw    = (const float*)d_in[16];
    const float* lb    = (const float*)d_in[17];
    const float* gnn_w = (const float*)d_in[18];
    const float* gnn_b = (const float*)d_in[19];
    const int*   bidx  = (const int*)d_in[20];
    float* out = (float*)d_out;

    constexpr int SFUSED_SMEM = 16 * Nn * 4;   // 128000 bytes

    static bool inited = false;
    static cudaStream_t s2;
    static cudaEvent_t evFork, evW, evB;
    static ushortT *pSh, *pSl, *pXh, *pXl, *pR1h, *pR1l;
    if (!inited) {
        cudaStreamCreateWithFlags(&s2, cudaStreamNonBlocking);
        cudaEventCreateWithFlags(&evFork, cudaEventDisableTiming);
        cudaEventCreateWithFlags(&evW,    cudaEventDisableTiming);
        cudaEventCreateWithFlags(&evB,    cudaEventDisableTiming);
        cudaFuncSetAttribute(k_sfused, cudaFuncAttributeMaxDynamicSharedMemorySize, SFUSED_SMEM);
        cudaGetSymbolAddress((void**)&pSh,  g_Sh);
        cudaGetSymbolAddress((void**)&pSl,  g_Sl);
        cudaGetSymbolAddress((void**)&pXh,  g_Xh);
        cudaGetSymbolAddress((void**)&pXl,  g_Xl);
        cudaGetSymbolAddress((void**)&pR1h, g_R1h);
        cudaGetSymbolAddress((void**)&pR1l, g_R1l);
        inited = true;
    }

    // fork branch stream
    cudaEventRecord(evFork, 0);
    cudaStreamWaitEvent(s2, evFork, 0);

    // ---- branch stream: everything independent of the GEMM chain ----
    k_proj<<<dim3(125, 1), 256, 0, s2>>>(ne, bp, Oo, 1);          // bias
    k_proj<<<dim3(125, 13), 256, 0, s2>>>(ne, wp, WCOLS, 0);      // W
    cudaEventRecord(evW, s2);                                     // bias+W ready
    k_proj<<<dim3(125, 1), 256, 0, s2>>>(ne, wwt_p, 128, 2);
    k_proj<<<dim3(125, 1), 256, 0, s2>>>(ne, wws_p, 32, 3);
    k_rs<<<Nn, 256, 0, s2>>>(gnn_w);
    k_uv<<<(Bb * Ee + 255) / 256, 256, 0, s2>>>(xew, bidx, lw, lb);
    k_hodge<<<dim3((Ee + 255) / 256, HCH), 256, 0, s2>>>(hodge);
    k_ybar<<<(Bb * Ee + 255) / 256, 256, 0, s2>>>(p_jmp);
    k_m<<<dim3((Nn + 31) / 32, MKS), 256, 0, s2>>>(inc);
    k_xw<<<(Bb * Nn + 255) / 256, 256, 0, s2>>>(xwin, Tp);
    k_asm_rest<<<Nn, 192, 0, s2>>>(zfc, gnn_b, out);              // cols 64..255
    cudaEventRecord(evB, s2);

    // ---- main stream: S -> GEMM chain -> diffusion epilogue ----
    k_sfused<<<125, 256, SFUSED_SMEM>>>(ne, p_sty, p_fix, adj);
    k_splitX<<<(Nn * BCP + 255) / 256, 256>>>(x);
    k_mmagemm<<<dim3(6, 32, KSP), 128>>>(pSh, pSl, pXh, pXl);
    k_reduce1<<<(Nn * BCP / 4 + 255) / 256, 256>>>();
    k_mmagemm<<<dim3(6, 32, KSP), 128>>>(pSh, pSl, pR1h, pR1l);
    k_reduce2<<<(Nn * BCP / 4 + 255) / 256, 256>>>();
    cudaStreamWaitEvent(0, evW, 0);
    k_asm_diff<<<Nn, 256>>>(x, out);                              // cols 0..63
    cudaStreamWaitEvent(0, evB, 0);                               // join
}

// round 6
// speedup vs baseline: 2.2920x; 1.1136x over previous
#include <cuda_runtime.h>
#include <cuda_bf16.h>
#include <math.h>

typedef unsigned short ushortT;
typedef unsigned int uintT;

// ---------------- problem dims ----------------
constexpr int Bb = 16, Nn = 2000, Ee = 3000, Cc = 17, Ww = 12, Dd = 16, Oo = 256, Kk = 3, NBt = 3;
constexpr int BCP   = 288;
constexpr int KC    = Kk * Cc;       // 51
constexpr int WCOLS = KC * 64;       // 3264
constexpr int HCH   = 16;
constexpr int MKS   = 4;
constexpr int KSP   = 8;             // GEMM split-K factor
constexpr int KBPS  = 16;            // k-blocks per split (8*16=128 >= 125)
constexpr int NKB   = 125;           // total k-blocks

// ---------------- scratch ----------------
__device__ __align__(16) float  g_cinv[Nn];
__device__ __align__(16) ushortT g_Sh[Nn * Nn];
__device__ __align__(16) ushortT g_Sl[Nn * Nn];
__device__ __align__(16) ushortT g_Xh[Nn * BCP];
__device__ __align__(16) ushortT g_Xl[Nn * BCP];
__device__ __align__(16) ushortT g_R1h[Nn * BCP];
__device__ __align__(16) ushortT g_R1l[Nn * BCP];
__device__ __align__(16) float  g_R1[Nn * BCP];
__device__ __align__(16) float  g_R2[Nn * BCP];
__device__ __align__(16) float  g_Cpart[KSP * Nn * BCP];
__device__ float g_W   [Nn * WCOLS];
__device__ float g_bias[Nn * Oo];
__device__ float g_wwt [Nn * 128];
__device__ float g_wws [Nn * 32];
__device__ float g_U[Bb * Ee];
__device__ float g_V[Bb * Ee];
__device__ float g_Hpart[HCH * Bb * Ee];
__device__ float g_Ybar[Bb * Ee];
__device__ float g_Mpart[MKS * Bb * Nn];
__device__ float g_XW[Bb * Nn];
__device__ float g_rs[Nn];

__device__ __forceinline__ float scalar_val(const void* p) {
    int v = *(const int*)p;
    if (v > -100000000 && v < 100000000) return (float)v;
    return __int_as_float(v);
}
__device__ __forceinline__ ushortT f2bf(float v) {
    __nv_bfloat16 b = __float2bfloat16(v);
    return *reinterpret_cast<ushortT*>(&b);
}
__device__ __forceinline__ float bf2f(ushortT u) {
    __nv_bfloat16 b; *reinterpret_cast<ushortT*>(&b) = u;
    return __bfloat162float(b);
}

__device__ __forceinline__ float blk_max(float v, float* red) {
    #pragma unroll
    for (int o = 16; o > 0; o >>= 1) v = fmaxf(v, __shfl_xor_sync(0xffffffffu, v, o));
    int t = threadIdx.x;
    if ((t & 31) == 0) red[t >> 5] = v;
    __syncthreads();
    if (t < 8) {
        v = red[t];
        #pragma unroll
        for (int o = 4; o > 0; o >>= 1) v = fmaxf(v, __shfl_xor_sync(0xffu, v, o));
        if (t == 0) red[0] = v;
    }
    __syncthreads();
    v = red[0];
    __syncthreads();
    return v;
}
__device__ __forceinline__ float blk_sum(float v, float* red) {
    #pragma unroll
    for (int o = 16; o > 0; o >>= 1) v += __shfl_xor_sync(0xffffffffu, v, o);
    int t = threadIdx.x;
    if ((t & 31) == 0) red[t >> 5] = v;
    __syncthreads();
    if (t < 8) {
        v = red[t];
        #pragma unroll
        for (int o = 4; o > 0; o >>= 1) v += __shfl_xor_sync(0xffu, v, o);
        if (t == 0) red[0] = v;
    }
    __syncthreads();
    v = red[0];
    __syncthreads();
    return v;
}

// ---------------- fused: S0 -> softmax -> bf16 split -> X split (per-strip) ----------------
// 8-row strips, 250 CTAs, 64KB dynamic smem.
__global__ void __launch_bounds__(256) k_sfused(const float* __restrict__ ne,
                                                const void* p_stay, const void* p_fixed,
                                                const float* __restrict__ adj,
                                                const float* __restrict__ x) {
    extern __shared__ float strip[];             // [8][Nn]
    __shared__ float neI[8][16];
    __shared__ float red[8];
    __shared__ float cinv_s[8];
    int i0 = blockIdx.x * 8;
    int t = threadIdx.x;
    if (t < 128) neI[t >> 4][t & 15] = ne[(i0 + (t >> 4)) * Dd + (t & 15)];
    __syncthreads();
    bool fixed = (scalar_val(p_fixed) != 0.f);
    float stay = scalar_val(p_stay);
    for (int j = t; j < Nn; j += 256) {
        float nj[16];
        const float4* njp = (const float4*)&ne[j * Dd];
        #pragma unroll
        for (int q = 0; q < 4; q++) {
            float4 v = njp[q];
            nj[q*4+0] = v.x; nj[q*4+1] = v.y; nj[q*4+2] = v.z; nj[q*4+3] = v.w;
        }
        #pragma unroll
        for (int r = 0; r < 8; r++) {
            float acc = 0.f;
            #pragma unroll
            for (int d = 0; d < 16; d++) acc += neI[r][d] * nj[d];
            acc = fmaxf(acc, 0.f);
            if (i0 + r == j) acc = stay;
            strip[r * Nn + j] = acc;
        }
    }
    __syncthreads();
    #pragma unroll 1
    for (int r = 0; r < 8; r++) {
        size_t rowoff = (size_t)(i0 + r) * Nn;
        float* row = &strip[r * Nn];
        float outsum;
        if (!fixed) {
            float m = -1e30f;
            for (int j = t; j < Nn; j += 256) m = fmaxf(m, row[j]);
            m = blk_max(m, red);
            float s = 0.f;
            for (int j = t; j < Nn; j += 256) { float e = __expf(row[j] - m); row[j] = e; s += e; }
            s = blk_sum(s, red);
            float inv = 1.f / s;
            float fs = 0.f;
            for (int j = t; j < Nn; j += 256) {
                float v = row[j] * inv;
                ushortT h = f2bf(v);
                g_Sh[rowoff + j] = h;
                g_Sl[rowoff + j] = f2bf(v - bf2f(h));
                fs += v;
            }
            outsum = blk_sum(fs, red);
        } else {
            float fs = 0.f;
            for (int j = t; j < Nn; j += 256) {
                float v = adj[rowoff + j] * __expf(row[j]);
                ushortT h = f2bf(v);
                g_Sh[rowoff + j] = h;
                g_Sl[rowoff + j] = f2bf(v - bf2f(h));
                fs += v;
            }
            outsum = blk_sum(fs, red);
        }
        if (t == 0) { float ci = 1.f / outsum; g_cinv[i0 + r] = ci; cinv_s[r] = ci; }
    }
    __syncthreads();
    // X split for this strip's rows: g_X{h,l}[m][q] for m in [i0, i0+8)
    for (int idx = t; idx < 8 * BCP; idx += 256) {
        int r = idx / BCP, q = idx - r * BCP;
        int m = i0 + r;
        float v = 0.f;
        if (q < Bb * Cc) {
            int b = q / Cc, c = q - b * Cc;
            v = x[((size_t)b * Nn + m) * Cc + c] * cinv_s[r];
        }
        ushortT h = f2bf(v);
        g_Xh[(size_t)m * BCP + q] = h;
        g_Xl[(size_t)m * BCP + q] = f2bf(v - bf2f(h));
    }
}

// ---------------- GEMM: cp.async double-buffered, split-K ----------------
__device__ __forceinline__ void ldsm_x4(uintT* r, uintT addr) {
    asm volatile("ldmatrix.sync.aligned.m8n8.x4.shared.b16 {%0,%1,%2,%3}, [%4];"
                 : "=r"(r[0]), "=r"(r[1]), "=r"(r[2]), "=r"(r[3]) : "r"(addr));
}
__device__ __forceinline__ void ldsm_x2t(uintT* r, uintT addr) {
    asm volatile("ldmatrix.sync.aligned.m8n8.x2.trans.shared.b16 {%0,%1}, [%2];"
                 : "=r"(r[0]), "=r"(r[1]) : "r"(addr));
}
__device__ __forceinline__ void mma16816(float* c, const uintT* a, const uintT* b) {
    asm volatile("mma.sync.aligned.m16n8k16.row.col.f32.bf16.bf16.f32 "
                 "{%0,%1,%2,%3}, {%4,%5,%6,%7}, {%8,%9}, {%0,%1,%2,%3};"
                 : "+f"(c[0]), "+f"(c[1]), "+f"(c[2]), "+f"(c[3])
                 : "r"(a[0]), "r"(a[1]), "r"(a[2]), "r"(a[3]), "r"(b[0]), "r"(b[1]));
}
__device__ __forceinline__ void cpa16(uintT s, const void* g) {
    asm volatile("cp.async.cg.shared.global [%0], [%1], 16;" :: "r"(s), "l"(g));
}

__global__ void __launch_bounds__(128) k_mmagemm(
        const ushortT* __restrict__ Ah, const ushortT* __restrict__ Al,
        const ushortT* __restrict__ Bh, const ushortT* __restrict__ Bl) {
    constexpr int ASTR = 24;
    constexpr int BSTR = 56;
    __shared__ ushortT sAh[2][64 * ASTR], sAl[2][64 * ASTR];
    __shared__ ushortT sBh[2][16 * BSTR], sBl[2][16 * BSTR];

    int t = threadIdx.x;
    int warp = t >> 5, lane = t & 31;
    int wm = (warp >> 1) * 32, wn = (warp & 1) * 24;
    int bm0 = blockIdx.y * 64, bn0 = blockIdx.x * 48;
    int kb_begin = blockIdx.z * KBPS;
    int kb_end   = min(kb_begin + KBPS, NKB);

    int ar = t >> 1, ak = (t & 1) * 8;
    int br = t / 6,  bs = t % 6;
    bool bact = t < 96;

    // clamp A row (rows >= Nn produce garbage outputs that are never stored)
    int gr = bm0 + ar; if (gr >= Nn) gr = Nn - 1;

    float acc[2][3][4];
    #pragma unroll
    for (int i = 0; i < 2; i++)
        #pragma unroll
        for (int j = 0; j < 3; j++)
            #pragma unroll
            for (int q = 0; q < 4; q++) acc[i][j][q] = 0.f;

    uintT bAh[2], bAl[2], bBh[2], bBl[2];
    bAh[0] = (uintT)__cvta_generic_to_shared(&sAh[0][0]);
    bAh[1] = (uintT)__cvta_generic_to_shared(&sAh[1][0]);
    bAl[0] = (uintT)__cvta_generic_to_shared(&sAl[0][0]);
    bAl[1] = (uintT)__cvta_generic_to_shared(&sAl[1][0]);
    bBh[0] = (uintT)__cvta_generic_to_shared(&sBh[0][0]);
    bBh[1] = (uintT)__cvta_generic_to_shared(&sBh[1][0]);
    bBl[0] = (uintT)__cvta_generic_to_shared(&sBl[0][0]);
    bBl[1] = (uintT)__cvta_generic_to_shared(&sBl[1][0]);
    uintT awB = (uintT)(ar * ASTR + ak) * 2;
    uintT bwB = (uintT)(br * BSTR + bs * 8) * 2;

    // prologue: async-load tile kb_begin into buffer 0
    {
        size_t aoff = (size_t)gr * Nn + kb_begin * 16 + ak;
        cpa16(bAh[0] + awB, Ah + aoff);
        cpa16(bAl[0] + awB, Al + aoff);
        if (bact) {
            size_t boff = (size_t)(kb_begin * 16 + br) * BCP + bn0 + bs * 8;
            cpa16(bBh[0] + bwB, Bh + boff);
            cpa16(bBl[0] + bwB, Bl + boff);
        }
        asm volatile("cp.async.commit_group;");
        asm volatile("cp.async.wait_group 0;");
    }
    __syncthreads();

    uintT aoffB = ((wm + (lane & 15)) * ASTR + ((lane & 16) ? 8 : 0)) * 2;
    uintT boffB = ((lane & 15) * BSTR + wn) * 2;

    for (int kb = kb_begin; kb < kb_end; kb++) {
        int cur = (kb - kb_begin) & 1;
        bool more = (kb + 1 < kb_end);
        if (more) {
            int nxt = cur ^ 1;
            size_t aoff = (size_t)gr * Nn + (kb + 1) * 16 + ak;
            cpa16(bAh[nxt] + awB, Ah + aoff);
            cpa16(bAl[nxt] + awB, Al + aoff);
            if (bact) {
                size_t boff = (size_t)((kb + 1) * 16 + br) * BCP + bn0 + bs * 8;
                cpa16(bBh[nxt] + bwB, Bh + boff);
                cpa16(bBl[nxt] + bwB, Bl + boff);
            }
            asm volatile("cp.async.commit_group;");
        }
        uintT fah[2][4], fal[2][4], fbh[3][2], fbl[3][2];
        #pragma unroll
        for (int mt = 0; mt < 2; mt++) {
            ldsm_x4(fah[mt], bAh[cur] + aoffB + mt * 16 * ASTR * 2);
            ldsm_x4(fal[mt], bAl[cur] + aoffB + mt * 16 * ASTR * 2);
        }
        #pragma unroll
        for (int nt = 0; nt < 3; nt++) {
            ldsm_x2t(fbh[nt], bBh[cur] + boffB + nt * 16);
            ldsm_x2t(fbl[nt], bBl[cur] + boffB + nt * 16);
        }
        #pragma unroll
        for (int mt = 0; mt < 2; mt++)
            #pragma unroll
            for (int nt = 0; nt < 3; nt++) {
                mma16816(acc[mt][nt], fah[mt], fbh[nt]);
                mma16816(acc[mt][nt], fah[mt], fbl[nt]);
                mma16816(acc[mt][nt], fal[mt], fbh[nt]);
            }
        if (more) {
            asm volatile("cp.async.wait_group 0;");
        }
        __syncthreads();
    }
    float* Cp = g_Cpart + (size_t)blockIdx.z * Nn * BCP;
    #pragma unroll
    for (int mt = 0; mt < 2; mt++)
        #pragma unroll
        for (int nt = 0; nt < 3; nt++) {
            int row = bm0 + wm + mt * 16 + (lane >> 2);
            int col = bn0 + wn + nt * 8 + (lane & 3) * 2;
            if (row < Nn)
                *(float2*)&Cp[(size_t)row * BCP + col] = make_float2(acc[mt][nt][0], acc[mt][nt][1]);
            if (row + 8 < Nn)
                *(float2*)&Cp[(size_t)(row + 8) * BCP + col] = make_float2(acc[mt][nt][2], acc[mt][nt][3]);
        }
}

// ---------------- reduce partials -> R1 fp32 + scaled bf16 hi/lo ----------------
__global__ void k_reduce1() {
    int i4 = blockIdx.x * 256 + threadIdx.x;
    if (i4 >= Nn * BCP / 4) return;
    float4 s = make_float4(0.f, 0.f, 0.f, 0.f);
    #pragma unroll
    for (int sp = 0; sp < KSP; sp++) {
        float4 p = ((const float4*)g_Cpart)[(size_t)sp * (Nn * BCP / 4) + i4];
        s.x += p.x; s.y += p.y; s.z += p.z; s.w += p.w;
    }
    ((float4*)g_R1)[i4] = s;
    int m = (i4 * 4) / BCP;
    float ci = g_cinv[m];
    float v[4] = { s.x * ci, s.y * ci, s.z * ci, s.w * ci };
    ushort4 hh, ll;
    ushortT* hp = &hh.x; ushortT* lp = &ll.x;
    #pragma unroll
    for (int q = 0; q < 4; q++) {
        ushortT h = f2bf(v[q]);
        hp[q] = h;
        lp[q] = f2bf(v[q] - bf2f(h));
    }
    ((ushort4*)g_R1h)[i4] = hh;
    ((ushort4*)g_R1l)[i4] = ll;
}

__global__ void k_reduce2() {
    int i4 = blockIdx.x * 256 + threadIdx.x;
    if (i4 >= Nn * BCP / 4) return;
    float4 s = make_float4(0.f, 0.f, 0.f, 0.f);
    #pragma unroll
    for (int sp = 0; sp < KSP; sp++) {
        float4 p = ((const float4*)g_Cpart)[(size_t)sp * (Nn * BCP / 4) + i4];
        s.x += p.x; s.y += p.y; s.z += p.z; s.w += p.w;
    }
    ((float4*)g_R2)[i4] = s;
}

// ---------------- W projection (3264 cols) ----------------
__global__ void k_projW(const float* __restrict__ ne, const float* __restrict__ pool) {
    __shared__ float p_s[16][256];
    __shared__ float ne_s[16][17];
    int n0 = blockIdx.x * 16;
    int c0 = blockIdx.y * 256;
    int t = threadIdx.x;
    for (int d = 0; d < 16; d++)
        p_s[d][t] = (c0 + t < WCOLS) ? pool[(size_t)d * WCOLS + c0 + t] : 0.f;
    { int nn = t >> 4, d = t & 15; ne_s[nn][d] = ne[(n0 + nn) * 16 + d]; }
    __syncthreads();
    int c = c0 + t;
    if (c >= WCOLS) return;
    for (int nn = 0; nn < 16; nn++) {
        float acc = 0.f;
        #pragma unroll
        for (int d = 0; d < 16; d++) acc += ne_s[nn][d] * p_s[d][t];
        g_W[(size_t)(n0 + nn) * WCOLS + c] = acc;
    }
}

// ---------------- merged small projections: bias(256) + wwt(128) + wws(32) ----------------
__global__ void k_projS(const float* __restrict__ ne, const float* __restrict__ bp,
                        const float* __restrict__ wwt_p, const float* __restrict__ wws_p) {
    __shared__ float p_s[16][224];
    __shared__ float ne_s[16][17];
    int n0 = blockIdx.x * 16;
    int c0 = blockIdx.y * 224;     // 2 blocks: [0,224), [224,416)
    int t = threadIdx.x;           // 224 threads
    int c = c0 + t;
    for (int d = 0; d < 16; d++) {
        float pv = 0.f;
        if (c < 256)       pv = bp[(size_t)d * Oo + c];
        else if (c < 384)  pv = wwt_p[(size_t)d * 128 + (c - 256)];
        else if (c < 416)  pv = wws_p[(size_t)d * 32 + (c - 384)];
        p_s[d][t] = pv;
    }
    if (t < 128) { int nn = t >> 3; int d0 = (t & 7) * 2;
        ne_s[nn][d0] = ne[(n0 + nn) * 16 + d0];
        ne_s[nn][d0+1] = ne[(n0 + nn) * 16 + d0+1]; }
    __syncthreads();
    if (c >= 416) return;
    for (int nn = 0; nn < 16; nn++) {
        float acc = 0.f;
        #pragma unroll
        for (int d = 0; d < 16; d++) acc += ne_s[nn][d] * p_s[d][t];
        int n = n0 + nn;
        if (c < 256)      g_bias[(size_t)n * Oo + c] = acc;
        else if (c < 384) g_wwt[(size_t)n * 128 + (c - 256)] = acc;
        else              g_wws[(size_t)n * 32 + (c - 384)] = acc;
    }
}

// ---------------- gnn_w row sums ----------------
__global__ void k_rs(const float* __restrict__ gnn_w) {
    __shared__ float red[8];
    int m = blockIdx.x, t = threadIdx.x;
    float s = 0.f;
    for (int j = t; j < Nn; j += 256) s += gnn_w[(size_t)m * Nn + j];
    s = blk_sum(s, red);
    if (t == 0) g_rs[m] = s;
}

// ---------------- U,V ----------------
__global__ void k_uv(const float* __restrict__ xew, const int* __restrict__ bidx,
                     const float* __restrict__ lw, const float* __restrict__ lb) {
    int idx = blockIdx.x * 256 + threadIdx.x;
    if (idx >= Bb * Ee) return;
    int b = idx / Ee, i = idx % Ee;
    float w = lw[0], bia = lb[0];
    float u = 0.f, v = 0.f;
    #pragma unroll
    for (int f = 0; f < NBt; f++) {
        int tt = bidx[f]; tt = max(0, min(Ww - 1, tt));
        float xv = xew[((size_t)(b * Ww + tt)) * Ee + i] * w + bia;
        u += xv; v += (float)(NBt - 1 - f) * xv;
    }
    g_U[idx] = u; g_V[idx] = v;
}

// ---------------- hodge partials ----------------
__global__ void k_hodge(const float* __restrict__ hodge) {
    __shared__ float u_s[16][192];
    constexpr int CL = (Ee + HCH - 1) / HCH; // 188
    int ch = blockIdx.y;
    int i0 = ch * CL;
    int ilen = min(CL, Ee - i0);
    int t = threadIdx.x;
    for (int idx = t; idx < Bb * ilen; idx += 256) {
        int bb = idx / ilen, ii = idx % ilen;
        u_s[bb][ii] = g_U[bb * Ee + i0 + ii];
    }
    __syncthreads();
    int j = blockIdx.x * 256 + t;
    if (j >= Ee) return;
    float acc[16];
    #pragma unroll
    for (int bb = 0; bb < 16; bb++) acc[bb] = 0.f;
    for (int ii = 0; ii < ilen; ii++) {
        float h = hodge[(size_t)(i0 + ii) * Ee + j];
        #pragma unroll
        for (int bb = 0; bb < 16; bb++) acc[bb] += u_s[bb][ii] * h;
    }
    #pragma unroll
    for (int bb = 0; bb < 16; bb++)
        g_Hpart[((size_t)ch * Bb + bb) * Ee + j] = acc[bb];
}

__global__ void k_ybar(const void* p_jump) {
    int idx = blockIdx.x * 256 + threadIdx.x;
    if (idx >= Bb * Ee) return;
    int b = idx / Ee, j = idx % Ee;
    float jump = scalar_val(p_jump);
    float s = jump * g_V[idx];
    #pragma unroll
    for (int ch = 0; ch < HCH; ch++) s += g_Hpart[((size_t)ch * Bb + b) * Ee + j];
    g_Ybar[idx] = s * (1.f / (float)NBt);
}

// ---------------- Mpart ----------------
__global__ void k_m(const float* __restrict__ inc) {
    __shared__ float inc_s[32][65];
    __shared__ float yb_s[16][64];
    constexpr int SL = Ee / MKS; // 750
    int n0 = blockIdx.x * 32;
    int sp = blockIdx.y;
    int e_start = sp * SL, e_end = e_start + SL;
    int t = threadIdx.x;
    int nl = t & 31, bg = t >> 5;
    int b0 = bg * 2, b1 = bg * 2 + 1;
    float acc0 = 0.f, acc1 = 0.f;
    for (int e0 = e_start; e0 < e_end; e0 += 64) {
        for (int idx = t; idx < 32 * 64; idx += 256) {
            int r = idx >> 6, c = idx & 63;
            int n = n0 + r, e = e0 + c;
            inc_s[r][c] = (n < Nn && e < e_end) ? inc[(size_t)n * Ee + e] : 0.f;
        }
        for (int idx = t; idx < 16 * 64; idx += 256) {
            int bb = idx >> 6, c = idx & 63;
            int e = e0 + c;
            yb_s[bb][c] = (e < e_end) ? g_Ybar[bb * Ee + e] : 0.f;
        }
        __syncthreads();
        #pragma unroll
        for (int c = 0; c < 64; c++) {
            float w = inc_s[nl][c];
            acc0 += yb_s[b0][c] * w;
            acc1 += yb_s[b1][c] * w;
        }
        __syncthreads();
    }
    int n = n0 + nl;
    if (n < Nn) {
        g_Mpart[((size_t)sp * Bb + b0) * Nn + n] = acc0;
        g_Mpart[((size_t)sp * Bb + b1) * Nn + n] = acc1;
    }
}

// ---------------- XW ----------------
__global__ void k_xw(const float* __restrict__ xwin, const float* __restrict__ Tp) {
    int idx = blockIdx.x * 256 + threadIdx.x;
    if (idx >= Bb * Nn) return;
    int b = idx / Nn, n = idx % Nn;
    float s = 0.f;
    #pragma unroll
    for (int t = 0; t < Ww; t++) s += xwin[((size_t)(b * Ww + t)) * Nn + n] * Tp[t];
    g_XW[idx] = s;
}

// ---------------- diffusion assembly: cols 0..63 ----------------
__global__ void k_asm_diff(const float* __restrict__ x, float* __restrict__ out) {
    __shared__ float xs_s[16][52];
    int n = blockIdx.x;
    int t = threadIdx.x;
    for (int idx = t; idx < Bb * KC; idx += 256) {
        int b = idx / KC, ki = idx % KC;
        int k = ki / Cc, c = ki % Cc;
        float v;
        if (k == 0)      v = x[((size_t)b * Nn + n) * Cc + c];
        else if (k == 1) v = g_R1[(size_t)n * BCP + b * Cc + c];
        else             v = g_R2[(size_t)n * BCP + b * Cc + c];
        xs_s[b][ki] = v;
    }
    __syncthreads();
    int o = t;
    if (o >= 64) return;
    float biasv = g_bias[(size_t)n * Oo + o];
    float w[KC];
    #pragma unroll
    for (int ki = 0; ki < KC; ki++) w[ki] = g_W[(size_t)n * WCOLS + ki * 64 + o];
    for (int b = 0; b < 16; b++) {
        float acc = 0.f;
        #pragma unroll
        for (int ki = 0; ki < KC; ki++) acc += xs_s[b][ki] * w[ki];
        out[((size_t)b * Nn + n) * Oo + o] = acc + biasv;
    }
}

// ---------------- rest assembly: cols 64..255 ----------------
__global__ void k_asm_rest(const float* __restrict__ zfc_in, const float* __restrict__ gnn_b,
                           float* __restrict__ out) {
    __shared__ float zfc_s[16][32];
    __shared__ float xw_s[16];
    __shared__ float m_s[16];
    int n = blockIdx.x;
    int t = threadIdx.x;   // 0..191
    for (int idx = t; idx < Bb * 32; idx += 192)
        zfc_s[idx >> 5][idx & 31] = zfc_in[idx];
    if (t < 16) {
        xw_s[t] = g_XW[t * Nn + n];
        float ms = 0.f;
        #pragma unroll
        for (int sp = 0; sp < MKS; sp++) ms += g_Mpart[((size_t)sp * Bb + t) * Nn + n];
        m_s[t] = ms;
    }
    __syncthreads();
    int o = 64 + t;
    float biasv = g_bias[(size_t)n * Oo + o];
    if (o < 96) {
        int c = o - 64;
        int flat = n * 32 + c;
        int r = flat / Nn;
        int m = flat - r * Nn;
        float rsv = g_rs[m], gb = gnn_b[m];
        for (int b = 0; b < 16; b++) {
            float v = fmaxf(zfc_s[b][r] * rsv + gb, 0.f);
            out[((size_t)b * Nn + n) * Oo + o] = v + biasv;
        }
    } else if (o < 224) {
        float wv = g_wwt[(size_t)n * 128 + (o - 96)];
        for (int b = 0; b < 16; b++)
            out[((size_t)b * Nn + n) * Oo + o] = xw_s[b] * wv + biasv;
    } else {
        float wv = g_wws[(size_t)n * 32 + (o - 224)];
        for (int b = 0; b < 16; b++)
            out[((size_t)b * Nn + n) * Oo + o] = m_s[b] * wv + biasv;
    }
}

// ---------------- host launch ----------------
extern "C" void kernel_launch(void* const* d_in, const int* in_sizes, int n_in,
                              void* d_out, int out_size) {
    const float* x     = (const float*)d_in[0];
    const float* xwin  = (const float*)d_in[1];
    const float* ne    = (const float*)d_in[2];
    const void*  p_fix = d_in[3];
    const float* adj   = (const float*)d_in[4];
    const void*  p_sty = d_in[5];
    const void*  p_jmp = d_in[6];
    const float* zfc   = (const float*)d_in[7];
    const float* hodge = (const float*)d_in[8];
    const float* xew   = (const float*)d_in[9];
    const float* inc   = (const float*)d_in[10];
    const float* wp    = (const float*)d_in[11];
    const float* wws_p = (const float*)d_in[12];
    const float* wwt_p = (const float*)d_in[13];
    const float* bp    = (const float*)d_in[14];
    const float* Tp    = (const float*)d_in[15];
    const float* lw    = (const float*)d_in[16];
    const float* lb    = (const float*)d_in[17];
    const float* gnn_w = (const float*)d_in[18];
    const float* gnn_b = (const float*)d_in[19];
    const int*   bidx  = (const int*)d_in[20];
    float* out = (float*)d_out;

    constexpr int SFUSED_SMEM = 8 * Nn * 4;   // 64000 bytes

    static bool inited = false;
    static cudaStream_t s2;
    static cudaEvent_t evFork, evW, evB;
    static ushortT *pSh, *pSl, *pXh, *pXl, *pR1h, *pR1l;
    if (!inited) {
        cudaStreamCreateWithFlags(&s2, cudaStreamNonBlocking);
        cudaEventCreateWithFlags(&evFork, cudaEventDisableTiming);
        cudaEventCreateWithFlags(&evW,    cudaEventDisableTiming);
        cudaEventCreateWithFlags(&evB,    cudaEventDisableTiming);
        cudaFuncSetAttribute(k_sfused, cudaFuncAttributeMaxDynamicSharedMemorySize, SFUSED_SMEM);
        cudaGetSymbolAddress((void**)&pSh,  g_Sh);
        cudaGetSymbolAddress((void**)&pSl,  g_Sl);
        cudaGetSymbolAddress((void**)&pXh,  g_Xh);
        cudaGetSymbolAddress((void**)&pXl,  g_Xl);
        cudaGetSymbolAddress((void**)&pR1h, g_R1h);
        cudaGetSymbolAddress((void**)&pR1l, g_R1l);
        inited = true;
    }

    // fork branch stream
    cudaEventRecord(evFork, 0);
    cudaStreamWaitEvent(s2, evFork, 0);

    // ---- branch stream ----
    k_projS<<<dim3(125, 2), 224, 0, s2>>>(ne, bp, wwt_p, wws_p);   // bias+wwt+wws
    k_projW<<<dim3(125, 13), 256, 0, s2>>>(ne, wp);                // W
    cudaEventRecord(evW, s2);
    k_rs<<<Nn, 256, 0, s2>>>(gnn_w);
    k_uv<<<(Bb * Ee + 255) / 256, 256, 0, s2>>>(xew, bidx, lw, lb);
    k_hodge<<<dim3((Ee + 255) / 256, HCH), 256, 0, s2>>>(hodge);
    k_ybar<<<(Bb * Ee + 255) / 256, 256, 0, s2>>>(p_jmp);
    k_m<<<dim3((Nn + 31) / 32, MKS), 256, 0, s2>>>(inc);
    k_xw<<<(Bb * Nn + 255) / 256, 256, 0, s2>>>(xwin, Tp);
    k_asm_rest<<<Nn, 192, 0, s2>>>(zfc, gnn_b, out);
    cudaEventRecord(evB, s2);

    // ---- main stream: S -> GEMM chain -> diffusion epilogue ----
    k_sfused<<<250, 256, SFUSED_SMEM>>>(ne, p_sty, p_fix, adj, x);
    k_mmagemm<<<dim3(6, 32, KSP), 128>>>(pSh, pSl, pXh, pXl);
    k_reduce1<<<(Nn * BCP / 4 + 255) / 256, 256>>>();
    k_mmagemm<<<dim3(6, 32, KSP), 128>>>(pSh, pSl, pR1h, pR1l);
    k_reduce2<<<(Nn * BCP / 4 + 255) / 256, 256>>>();
    cudaStreamWaitEvent(0, evW, 0);
    k_asm_diff<<<Nn, 256>>>(x, out);
    cudaStreamWaitEvent(0, evB, 0);
}